// round 6
// baseline (speedup 1.0000x reference)
#include <cuda_runtime.h>
#include <math.h>
#include <cstdint>

#define BB 256
#define TT 256
#define CC 1024
#define DD 64
#define BT (BB*TT)

// Scratch: Q, K, V (16 MB each, stored as tf32-exact fp32) + transposed W
__device__ float g_q[BT*DD];
__device__ float g_k[BT*DD];
__device__ float g_v[BT*DD];
__device__ float g_wt[192*1024];   // K-major, tf32-rounded

// ===================== PTX helpers (sm_80+ PTX, ok on compute_103) =========
__device__ __forceinline__ uint32_t f32_to_tf32(float f) {
    uint32_t u;
    asm("cvt.rna.tf32.f32 %0, %1;" : "=r"(u) : "f"(f));
    return u;
}

__device__ __forceinline__ void mma_tf32_16n8k8(
    float d[4], const uint32_t a[4], const uint32_t b[2])
{
    asm volatile(
        "mma.sync.aligned.m16n8k8.row.col.f32.tf32.tf32.f32 "
        "{%0,%1,%2,%3}, {%4,%5,%6,%7}, {%8,%9}, {%0,%1,%2,%3};"
        : "+f"(d[0]), "+f"(d[1]), "+f"(d[2]), "+f"(d[3])
        : "r"(a[0]), "r"(a[1]), "r"(a[2]), "r"(a[3]),
          "r"(b[0]), "r"(b[1]));
}

__device__ __forceinline__ void ldmatrix_x4(uint32_t r[4], uint32_t addr) {
    asm volatile("ldmatrix.sync.aligned.m8n8.x4.shared.b16 {%0,%1,%2,%3}, [%4];"
        : "=r"(r[0]), "=r"(r[1]), "=r"(r[2]), "=r"(r[3]) : "r"(addr));
}

__device__ __forceinline__ void cp_async16(uint32_t dst, const void* src) {
    asm volatile("cp.async.cg.shared.global [%0], [%1], 16;"
        :: "r"(dst), "l"(src) : "memory");
}
#define CP_COMMIT() asm volatile("cp.async.commit_group;" ::: "memory")
#define CP_WAIT1()  asm volatile("cp.async.wait_group 1;" ::: "memory")
#define CP_WAIT0()  asm volatile("cp.async.wait_group 0;" ::: "memory")

__device__ __forceinline__ uint32_t smem_u32(const void* p) {
    uint32_t a;
    asm("{ .reg .u64 t; cvta.to.shared.u64 t, %1; cvt.u32.u64 %0, t; }"
        : "=r"(a) : "l"(p));
    return a;
}

// ===================== Kernel 0: transpose W into K-major, tf32-rounded ====
__global__ __launch_bounds__(256) void transpose_w_kernel(
    const float* __restrict__ Wq, const float* __restrict__ Wk,
    const float* __restrict__ Wv)
{
    int n = blockIdx.x;                                 // 0..191
    const float* W = (n < 64) ? Wq : ((n < 128) ? Wk : Wv);
    int col = n & 63;
    for (int k = threadIdx.x; k < 1024; k += 256)
        g_wt[(size_t)n * 1024 + k] =
            __uint_as_float(f32_to_tf32(W[(size_t)k * 64 + col]));
}

// ===================== Kernel A: QKV via tf32 mma ==========================
// 512 CTAs x 256 thr (8 warps = 2 M x 4 N). CTA tile 128x192, warp 64x48.
// 32 K-chunks of 32, double-buffered. A (x): LDG + cvt.rna + STS (zero-mean
// rounding). B (Wt, pre-rounded): cp.async. Outputs rounded to tf32 so the
// attention kernel can use cp.async (HW truncation exact on tf32 values).

#define STRW 36
#define A_ROWS 128
#define B_ROWS 192
#define CHUNK_BYTES ((A_ROWS + B_ROWS) * STRW * 4)   // 46080
#define B_OFF (A_ROWS * STRW * 4)                    // 18432
#define QKV_SMEM (2 * CHUNK_BYTES)                   // 92160

__global__ __launch_bounds__(256, 2) void qkv_mma_kernel(
    const float* __restrict__ x)
{
    extern __shared__ float smf[];
    const uint32_t sbase = smem_u32(smf);
    const int tid    = threadIdx.x;
    const int lane   = tid & 31;
    const int wid    = tid >> 5;
    const int warp_m = wid >> 2;       // 0..1
    const int warp_n = wid & 3;        // 0..3
    const int row0   = blockIdx.x * 128;

    const int lr = lane >> 2;
    const int lc = lane & 3;

    float acc[4][6][4];
    #pragma unroll
    for (int mt = 0; mt < 4; mt++)
        #pragma unroll
        for (int nt = 0; nt < 6; nt++)
            #pragma unroll
            for (int i = 0; i < 4; i++) acc[mt][nt][i] = 0.f;

    const int a_r   = tid >> 3;        // 0..31 (base row; +32 per l)
    const int a_seg = tid & 7;

    float4 ra[4];
    auto ldg_a = [&](int c) {
        const int kc = c * 32;
        #pragma unroll
        for (int l = 0; l < 4; l++) {
            int r = a_r + l * 32;
            ra[l] = *(const float4*)&x[(size_t)(row0 + r) * CC + kc + a_seg * 4];
        }
    };
    auto sts_a = [&](uint32_t buf) {
        #pragma unroll
        for (int l = 0; l < 4; l++) {
            int r = a_r + l * 32;
            uint4 u = make_uint4(f32_to_tf32(ra[l].x), f32_to_tf32(ra[l].y),
                                 f32_to_tf32(ra[l].z), f32_to_tf32(ra[l].w));
            *(uint4*)(smf + ((buf - sbase) >> 2) + r * STRW + a_seg * 4) = u;
        }
    };
    auto cp_b = [&](int c, uint32_t buf) {
        const int kc = c * 32;
        #pragma unroll
        for (int l = 0; l < 6; l++) {
            int n = a_r + l * 32;      // 0..191
            cp_async16(buf + B_OFF + (uint32_t)(n * STRW + a_seg * 4) * 4,
                       &g_wt[(size_t)n * 1024 + kc + a_seg * 4]);
        }
    };

    // ldmatrix per-thread address offsets (bytes)
    const uint32_t aoff =
        ((uint32_t)(warp_m * 64 + (lane & 15)) * STRW + (lane >> 4) * 4) * 4;
    const uint32_t boff =
        ((uint32_t)(warp_n * 48 + (lane & 7) + (lane >> 4) * 8) * STRW
         + ((lane >> 3) & 1) * 4) * 4;

    // prologue
    ldg_a(0); sts_a(sbase);
    cp_b(0, sbase); CP_COMMIT();
    cp_b(1, sbase + CHUNK_BYTES); CP_COMMIT();
    ldg_a(1);                       // held in ra for iteration 0's sts

    for (int c = 0; c < 32; c++) {
        CP_WAIT1();
        __syncthreads();

        const uint32_t buf   = sbase + (uint32_t)(c & 1) * CHUNK_BYTES;
        const uint32_t abase = buf + aoff;
        const uint32_t bbase = buf + B_OFF + boff;

        #pragma unroll
        for (int ks = 0; ks < 4; ks++) {
            uint32_t af[4][4];
            #pragma unroll
            for (int mt = 0; mt < 4; mt++)
                ldmatrix_x4(af[mt], abase + mt * (16 * STRW * 4) + ks * 32);
            uint32_t bf[12];
            #pragma unroll
            for (int j = 0; j < 3; j++)
                ldmatrix_x4(&bf[j * 4], bbase + j * (16 * STRW * 4) + ks * 32);
            #pragma unroll
            for (int mt = 0; mt < 4; mt++)
                #pragma unroll
                for (int nt = 0; nt < 6; nt++)
                    mma_tf32_16n8k8(acc[mt][nt], af[mt],
                                    &bf[(nt >> 1) * 4 + (nt & 1) * 2]);
        }

        // A for chunk c+1 goes into the other buffer (safe: chunk c-1 fully
        // consumed by all warps before this iteration's top barrier)
        if (c + 1 < 32) {
            sts_a(sbase + (uint32_t)((c + 1) & 1) * CHUNK_BYTES);
            if (c + 2 < 32) ldg_a(c + 2);
        }
        __syncthreads();

        if (c + 2 < 32) cp_b(c + 2, buf);
        CP_COMMIT();
    }

    // epilogue: round to tf32, scatter to g_q / g_k / g_v
    #pragma unroll
    for (int mt = 0; mt < 4; mt++) {
        int rg = row0 + warp_m * 64 + mt * 16 + lr;
        #pragma unroll
        for (int nt = 0; nt < 6; nt++) {
            int ng = warp_n * 48 + nt * 8 + lc * 2;
            int m  = ng >> 6;
            int d  = ng & 63;
            float* base = (m == 0) ? g_q : (m == 1) ? g_k : g_v;
            *(float2*)&base[(size_t)rg * DD + d] = make_float2(
                __uint_as_float(f32_to_tf32(acc[mt][nt][0])),
                __uint_as_float(f32_to_tf32(acc[mt][nt][1])));
            *(float2*)&base[(size_t)(rg + 8) * DD + d] = make_float2(
                __uint_as_float(f32_to_tf32(acc[mt][nt][2])),
                __uint_as_float(f32_to_tf32(acc[mt][nt][3])));
        }
    }
}

// ===================== Kernel B: attention via tf32 mma.sync ===============
// Q/K/V in gmem are tf32-exact -> cp.async staging (HW truncation = identity).
// K/V staged only for the causally needed prefix (q0+64 rows).

#define SK_STRIDE 68
#define SV_STRIDE 72
#define SP_STRIDE2 260
#define SO_STRIDE 66
#define SK_OFF 0
#define SK_SIZE (256*SK_STRIDE)
#define SV_OFF SK_SIZE
#define SV_SIZE (256*SV_STRIDE)
#define RED_OFF (SV_OFF + SV_SIZE)
#define ATT_SMEM ((RED_OFF + 256) * 4)

__global__ __launch_bounds__(256) void attn_kernel(float* __restrict__ out)
{
    extern __shared__ uint32_t smu[];
    uint32_t* sK   = smu + SK_OFF;
    uint32_t* sV   = smu + SV_OFF;
    float*    sRed = (float*)(smu + RED_OFF);
    uint32_t* sP   = smu + SK_OFF;               // reuse K region
    float*    sO   = (float*)(smu + SK_OFF);     // reuse after P dead

    const uint32_t sbase = smem_u32(smu);
    const int tid  = threadIdx.x;
    const int wid  = tid >> 5;
    const int lane = tid & 31;
    const int wm   = wid >> 1;
    const int wn   = wid & 1;
    const int lr   = lane >> 2;
    const int lc   = lane & 3;

    const int qt = blockIdx.x;
    const int bb = blockIdx.y;
    const int q0 = qt * 64;
    const int rows = q0 + 64;            // causal prefix length

    // ---- cp.async stage K,V prefix ----
    const float* kb = g_k + (size_t)bb * TT * DD;
    const float* vb = g_v + (size_t)bb * TT * DD;
    for (int idx = tid; idx < rows * 16; idx += 256) {
        int s   = idx >> 4;
        int sg  = idx & 15;
        cp_async16(sbase + (uint32_t)(SK_OFF + s * SK_STRIDE + sg * 4) * 4,
                   &kb[s * DD + sg * 4]);
        cp_async16(sbase + (uint32_t)(SV_OFF + s * SV_STRIDE + sg * 4) * 4,
                   &vb[s * DD + sg * 4]);
    }
    CP_COMMIT();

    // ---- Q fragments (already tf32-exact, plain loads) ----
    uint32_t qf[8][4];
    {
        const size_t gr = (size_t)(bb * TT + q0 + wm * 16 + lr) * DD;
        #pragma unroll
        for (int ks = 0; ks < 8; ks++) {
            int k = ks * 8 + lc;
            qf[ks][0] = __float_as_uint(g_q[gr + k]);
            qf[ks][1] = __float_as_uint(g_q[gr + 8 * DD + k]);
            qf[ks][2] = __float_as_uint(g_q[gr + k + 4]);
            qf[ks][3] = __float_as_uint(g_q[gr + 8 * DD + k + 4]);
        }
    }
    CP_WAIT0();
    __syncthreads();

    const int ntv = min(16, max(0, (q0 + 64 - wn * 128) / 8));

    // ---- QK^T ----
    float sacc[16][4];
    #pragma unroll
    for (int nt = 0; nt < 16; nt++)
        #pragma unroll
        for (int i = 0; i < 4; i++) sacc[nt][i] = 0.f;

    #pragma unroll
    for (int nt = 0; nt < 16; nt++) {
        if (nt >= ntv) break;
        const uint32_t* kp = sK + (wn * 128 + nt * 8 + lr) * SK_STRIDE;
        #pragma unroll
        for (int ks = 0; ks < 8; ks++) {
            uint32_t bfr[2];
            bfr[0] = kp[ks * 8 + lc];
            bfr[1] = kp[ks * 8 + lc + 4];
            mma_tf32_16n8k8(sacc[nt], qf[ks], bfr);
        }
    }

    // ---- scale + causal mask + row max ----
    const int row_g0 = q0 + wm * 16 + lr;
    float mrow[2] = {-INFINITY, -INFINITY};
    #pragma unroll
    for (int nt = 0; nt < 16; nt++) {
        if (nt >= ntv) break;
        #pragma unroll
        for (int i = 0; i < 4; i++) {
            int col = wn * 128 + nt * 8 + 2 * lc + (i & 1);
            int row = row_g0 + ((i >> 1) << 3);
            float v = sacc[nt][i] * 0.03125f;
            v = (col <= row) ? v : -INFINITY;
            sacc[nt][i] = v;
            if (i < 2) mrow[0] = fmaxf(mrow[0], v);
            else       mrow[1] = fmaxf(mrow[1], v);
        }
    }
    #pragma unroll
    for (int off = 1; off <= 2; off <<= 1) {
        mrow[0] = fmaxf(mrow[0], __shfl_xor_sync(0xFFFFFFFF, mrow[0], off));
        mrow[1] = fmaxf(mrow[1], __shfl_xor_sync(0xFFFFFFFF, mrow[1], off));
    }
    if (lc == 0) {
        sRed[wn * 64 + wm * 16 + lr]     = mrow[0];
        sRed[wn * 64 + wm * 16 + lr + 8] = mrow[1];
    }
    __syncthreads();

    float gm0 = fmaxf(sRed[wm * 16 + lr],     sRed[64 + wm * 16 + lr]);
    float gm1 = fmaxf(sRed[wm * 16 + lr + 8], sRed[64 + wm * 16 + lr + 8]);

    // ---- exp, store P (tf32 rna), partial sums ----
    float srow[2] = {0.f, 0.f};
    #pragma unroll
    for (int nt = 0; nt < 16; nt++) {
        if (nt >= ntv) break;
        float e0 = __expf(sacc[nt][0] - gm0);
        float e1 = __expf(sacc[nt][1] - gm0);
        float e2 = __expf(sacc[nt][2] - gm1);
        float e3 = __expf(sacc[nt][3] - gm1);
        srow[0] += e0 + e1;
        srow[1] += e2 + e3;
        uint32_t* p0 = sP + (wm * 16 + lr) * SP_STRIDE2 + wn * 128 + nt * 8 + 2 * lc;
        *(uint2*)p0 = make_uint2(f32_to_tf32(e0), f32_to_tf32(e1));
        uint32_t* p1 = p0 + 8 * SP_STRIDE2;
        *(uint2*)p1 = make_uint2(f32_to_tf32(e2), f32_to_tf32(e3));
    }
    #pragma unroll
    for (int off = 1; off <= 2; off <<= 1) {
        srow[0] += __shfl_xor_sync(0xFFFFFFFF, srow[0], off);
        srow[1] += __shfl_xor_sync(0xFFFFFFFF, srow[1], off);
    }
    if (lc == 0) {
        sRed[128 + wn * 64 + wm * 16 + lr]     = srow[0];
        sRed[128 + wn * 64 + wm * 16 + lr + 8] = srow[1];
    }
    __syncthreads();

    const float inv0 = 1.f / (sRed[128 + wm * 16 + lr] +
                              sRed[128 + 64 + wm * 16 + lr]);
    const float inv1 = 1.f / (sRed[128 + wm * 16 + lr + 8] +
                              sRed[128 + 64 + wm * 16 + lr + 8]);

    // ---- PV ----
    float oacc[8][4];
    #pragma unroll
    for (int nt = 0; nt < 8; nt++)
        #pragma unroll
        for (int i = 0; i < 4; i++) oacc[nt][i] = 0.f;

    for (int ks = 0; ks < ntv; ks++) {
        uint32_t af[4];
        const uint32_t* ap = sP + (wm * 16 + lr) * SP_STRIDE2 + wn * 128 + ks * 8;
        af[0] = ap[lc];
        af[1] = ap[8 * SP_STRIDE2 + lc];
        af[2] = ap[lc + 4];
        af[3] = ap[8 * SP_STRIDE2 + lc + 4];
        const uint32_t* vp = sV + (wn * 128 + ks * 8 + lc) * SV_STRIDE;
        #pragma unroll
        for (int nt = 0; nt < 8; nt++) {
            uint32_t bfr[2];
            bfr[0] = vp[nt * 8 + lr];
            bfr[1] = vp[4 * SV_STRIDE + nt * 8 + lr];
            mma_tf32_16n8k8(oacc[nt], af, bfr);
        }
    }
    __syncthreads();

    // ---- cross-warp_n reduction + output ----
    if (wn == 0) {
        #pragma unroll
        for (int nt = 0; nt < 8; nt++) {
            float* o0 = sO + (wm * 16 + lr) * SO_STRIDE + nt * 8 + 2 * lc;
            *(float2*)o0 = make_float2(oacc[nt][0], oacc[nt][1]);
            float* o1 = o0 + 8 * SO_STRIDE;
            *(float2*)o1 = make_float2(oacc[nt][2], oacc[nt][3]);
        }
    }
    __syncthreads();
    if (wn == 1) {
        const size_t orow = (size_t)(bb * TT + q0 + wm * 16 + lr) * DD;
        #pragma unroll
        for (int nt = 0; nt < 8; nt++) {
            const float* o0 = sO + (wm * 16 + lr) * SO_STRIDE + nt * 8 + 2 * lc;
            const float* o1 = o0 + 8 * SO_STRIDE;
            float2 r0 = make_float2((oacc[nt][0] + o0[0]) * inv0,
                                    (oacc[nt][1] + o0[1]) * inv0);
            float2 r1 = make_float2((oacc[nt][2] + o1[0]) * inv1,
                                    (oacc[nt][3] + o1[1]) * inv1);
            *(float2*)&out[orow + nt * 8 + 2 * lc] = r0;
            *(float2*)&out[orow + 8 * DD + nt * 8 + 2 * lc] = r1;
        }
    }
}

// ---------------------------------------------------------------------------
extern "C" void kernel_launch(void* const* d_in, const int* in_sizes, int n_in,
                              void* d_out, int out_size)
{
    (void)in_sizes; (void)n_in; (void)out_size;
    const float* x  = (const float*)d_in[0];
    const float* Wq = (const float*)d_in[1];
    const float* Wk = (const float*)d_in[2];
    const float* Wv = (const float*)d_in[3];
    float* out = (float*)d_out;

    cudaFuncSetAttribute(qkv_mma_kernel,
                         cudaFuncAttributeMaxDynamicSharedMemorySize, QKV_SMEM);
    cudaFuncSetAttribute(attn_kernel,
                         cudaFuncAttributeMaxDynamicSharedMemorySize, ATT_SMEM);

    transpose_w_kernel<<<192, 256>>>(Wq, Wk, Wv);
    qkv_mma_kernel<<<BT / 128, 256, QKV_SMEM>>>(x);
    attn_kernel<<<dim3(4, BB), 256, ATT_SMEM>>>(out);
}

// round 7
// speedup vs baseline: 1.1612x; 1.1612x over previous
#include <cuda_runtime.h>
#include <math.h>
#include <cstdint>

#define BB 256
#define TT 256
#define CC 1024
#define DD 64
#define BT (BB*TT)

// Scratch: Q, K, V (16 MB each, stored tf32-exact) + transposed W (tf32 rna)
__device__ float g_q[BT*DD];
__device__ float g_k[BT*DD];
__device__ float g_v[BT*DD];
__device__ float g_wt[192*1024];

// ===================== PTX helpers (sm_80+ PTX, ok on compute_103) =========
__device__ __forceinline__ uint32_t f32_to_tf32(float f) {
    uint32_t u;
    asm("cvt.rna.tf32.f32 %0, %1;" : "=r"(u) : "f"(f));
    return u;
}

__device__ __forceinline__ void mma_tf32_16n8k8(
    float d[4], const uint32_t a[4], const uint32_t b[2])
{
    asm volatile(
        "mma.sync.aligned.m16n8k8.row.col.f32.tf32.tf32.f32 "
        "{%0,%1,%2,%3}, {%4,%5,%6,%7}, {%8,%9}, {%0,%1,%2,%3};"
        : "+f"(d[0]), "+f"(d[1]), "+f"(d[2]), "+f"(d[3])
        : "r"(a[0]), "r"(a[1]), "r"(a[2]), "r"(a[3]),
          "r"(b[0]), "r"(b[1]));
}

__device__ __forceinline__ void ldmatrix_x4(uint32_t r[4], uint32_t addr) {
    asm volatile("ldmatrix.sync.aligned.m8n8.x4.shared.b16 {%0,%1,%2,%3}, [%4];"
        : "=r"(r[0]), "=r"(r[1]), "=r"(r[2]), "=r"(r[3]) : "r"(addr));
}

__device__ __forceinline__ void cp_async16(uint32_t dst, const void* src) {
    asm volatile("cp.async.cg.shared.global [%0], [%1], 16;"
        :: "r"(dst), "l"(src) : "memory");
}
#define CP_COMMIT() asm volatile("cp.async.commit_group;" ::: "memory")
#define CP_WAIT1()  asm volatile("cp.async.wait_group 1;" ::: "memory")
#define CP_WAIT0()  asm volatile("cp.async.wait_group 0;" ::: "memory")

__device__ __forceinline__ uint32_t smem_u32(const void* p) {
    uint32_t a;
    asm("{ .reg .u64 t; cvta.to.shared.u64 t, %1; cvt.u32.u64 %0, t; }"
        : "=r"(a) : "l"(p));
    return a;
}

// ===================== Kernel 0: transpose W into K-major, tf32 rna ========
__global__ __launch_bounds__(256) void transpose_w_kernel(
    const float* __restrict__ Wq, const float* __restrict__ Wk,
    const float* __restrict__ Wv)
{
    int n = blockIdx.x;                                 // 0..191
    const float* W = (n < 64) ? Wq : ((n < 128) ? Wk : Wv);
    int col = n & 63;
    for (int k = threadIdx.x; k < 1024; k += 256)
        g_wt[(size_t)n * 1024 + k] =
            __uint_as_float(f32_to_tf32(W[(size_t)k * 64 + col]));
}

// ===================== Kernel A: QKV via tf32 mma + cp.async + ldmatrix ====
// 512 CTAs x 256 thr (8 warps = 2 M x 4 N). CTA tile 128x192, warp 64x48.
// 32 K-chunks of 32, 2-stage cp.async pipeline for BOTH A (x, HW-truncated)
// and B (g_wt, pre-rounded rna -> truncation exact).
// x truncation bias (-2^-11 multiplicative) cancelled in the epilogue.

#define STRW 36
#define A_ROWS 128
#define B_ROWS 192
#define CHUNK_BYTES ((A_ROWS + B_ROWS) * STRW * 4)   // 46080
#define B_OFF (A_ROWS * STRW * 4)                    // 18432
#define QKV_SMEM (2 * CHUNK_BYTES)                   // 92160

__global__ __launch_bounds__(256, 2) void qkv_mma_kernel(
    const float* __restrict__ x)
{
    extern __shared__ float smf[];
    const uint32_t sbase = smem_u32(smf);
    const int tid    = threadIdx.x;
    const int lane   = tid & 31;
    const int wid    = tid >> 5;
    const int warp_m = wid >> 2;       // 0..1
    const int warp_n = wid & 3;        // 0..3
    const int row0   = blockIdx.x * 128;

    const int lr = lane >> 2;
    const int lc = lane & 3;

    float acc[4][6][4];
    #pragma unroll
    for (int mt = 0; mt < 4; mt++)
        #pragma unroll
        for (int nt = 0; nt < 6; nt++)
            #pragma unroll
            for (int i = 0; i < 4; i++) acc[mt][nt][i] = 0.f;

    const int a_r   = tid >> 3;
    const int a_seg = tid & 7;
    auto issue_chunk = [&](int c, uint32_t buf) {
        const int kc = c * 32;
        #pragma unroll
        for (int l = 0; l < 4; l++) {
            int r = a_r + l * 32;
            cp_async16(buf + (uint32_t)(r * STRW + a_seg * 4) * 4,
                       &x[(size_t)(row0 + r) * CC + kc + a_seg * 4]);
        }
        #pragma unroll
        for (int l = 0; l < 6; l++) {
            int n = a_r + l * 32;                // 0..191
            cp_async16(buf + B_OFF + (uint32_t)(n * STRW + a_seg * 4) * 4,
                       &g_wt[(size_t)n * 1024 + kc + a_seg * 4]);
        }
    };

    const uint32_t aoff =
        ((uint32_t)(warp_m * 64 + (lane & 15)) * STRW + (lane >> 4) * 4) * 4;
    const uint32_t boff =
        ((uint32_t)(warp_n * 48 + (lane & 7) + (lane >> 4) * 8) * STRW
         + ((lane >> 3) & 1) * 4) * 4;

    issue_chunk(0, sbase);               CP_COMMIT();
    issue_chunk(1, sbase + CHUNK_BYTES); CP_COMMIT();

    for (int c = 0; c < 32; c++) {
        CP_WAIT1();
        __syncthreads();

        const uint32_t buf   = sbase + (uint32_t)(c & 1) * CHUNK_BYTES;
        const uint32_t abase = buf + aoff;
        const uint32_t bbase = buf + B_OFF + boff;

        #pragma unroll
        for (int ks = 0; ks < 4; ks++) {
            uint32_t af[4][4];
            #pragma unroll
            for (int mt = 0; mt < 4; mt++)
                ldmatrix_x4(af[mt], abase + mt * (16 * STRW * 4) + ks * 32);
            uint32_t bf[12];
            #pragma unroll
            for (int j = 0; j < 3; j++)
                ldmatrix_x4(&bf[j * 4], bbase + j * (16 * STRW * 4) + ks * 32);
            #pragma unroll
            for (int mt = 0; mt < 4; mt++)
                #pragma unroll
                for (int nt = 0; nt < 6; nt++)
                    mma_tf32_16n8k8(acc[mt][nt], af[mt],
                                    &bf[(nt >> 1) * 4 + (nt & 1) * 2]);
        }
        __syncthreads();

        if (c + 2 < 32) issue_chunk(c + 2, buf);
        CP_COMMIT();
    }

    // epilogue: cancel x-truncation bias (+2^-11), round to tf32, scatter
    const float comp = 1.00048828125f;   // 1 + 2^-11
    #pragma unroll
    for (int mt = 0; mt < 4; mt++) {
        int rg = row0 + warp_m * 64 + mt * 16 + lr;
        #pragma unroll
        for (int nt = 0; nt < 6; nt++) {
            int ng = warp_n * 48 + nt * 8 + lc * 2;
            int m  = ng >> 6;
            int d  = ng & 63;
            float* base = (m == 0) ? g_q : (m == 1) ? g_k : g_v;
            *(float2*)&base[(size_t)rg * DD + d] = make_float2(
                __uint_as_float(f32_to_tf32(acc[mt][nt][0] * comp)),
                __uint_as_float(f32_to_tf32(acc[mt][nt][1] * comp)));
            *(float2*)&base[(size_t)(rg + 8) * DD + d] = make_float2(
                __uint_as_float(f32_to_tf32(acc[mt][nt][2] * comp)),
                __uint_as_float(f32_to_tf32(acc[mt][nt][3] * comp)));
        }
    }
}

// ===================== Kernel B: attention via tf32 mma.sync ===============
// Q/K/V in gmem are tf32-exact -> cp.async staging (HW truncation = identity).
// K/V staged only for the causally needed prefix (q0+64 rows).

#define SK_STRIDE 68
#define SV_STRIDE 72
#define SP_STRIDE2 260
#define SO_STRIDE 66
#define SK_OFF 0
#define SK_SIZE (256*SK_STRIDE)
#define SV_OFF SK_SIZE
#define SV_SIZE (256*SV_STRIDE)
#define RED_OFF (SV_OFF + SV_SIZE)
#define ATT_SMEM ((RED_OFF + 256) * 4)

__global__ __launch_bounds__(256) void attn_kernel(float* __restrict__ out)
{
    extern __shared__ uint32_t smu[];
    uint32_t* sK   = smu + SK_OFF;
    uint32_t* sV   = smu + SV_OFF;
    float*    sRed = (float*)(smu + RED_OFF);
    uint32_t* sP   = smu + SK_OFF;               // reuse K region
    float*    sO   = (float*)(smu + SK_OFF);     // reuse after P dead

    const uint32_t sbase = smem_u32(smu);
    const int tid  = threadIdx.x;
    const int wid  = tid >> 5;
    const int lane = tid & 31;
    const int wm   = wid >> 1;
    const int wn   = wid & 1;
    const int lr   = lane >> 2;
    const int lc   = lane & 3;

    const int qt = blockIdx.x;
    const int bb = blockIdx.y;
    const int q0 = qt * 64;
    const int rows = q0 + 64;            // causal prefix length

    const float* kb = g_k + (size_t)bb * TT * DD;
    const float* vb = g_v + (size_t)bb * TT * DD;
    for (int idx = tid; idx < rows * 16; idx += 256) {
        int s   = idx >> 4;
        int sg  = idx & 15;
        cp_async16(sbase + (uint32_t)(SK_OFF + s * SK_STRIDE + sg * 4) * 4,
                   &kb[s * DD + sg * 4]);
        cp_async16(sbase + (uint32_t)(SV_OFF + s * SV_STRIDE + sg * 4) * 4,
                   &vb[s * DD + sg * 4]);
    }
    CP_COMMIT();

    uint32_t qf[8][4];
    {
        const size_t gr = (size_t)(bb * TT + q0 + wm * 16 + lr) * DD;
        #pragma unroll
        for (int ks = 0; ks < 8; ks++) {
            int k = ks * 8 + lc;
            qf[ks][0] = __float_as_uint(g_q[gr + k]);
            qf[ks][1] = __float_as_uint(g_q[gr + 8 * DD + k]);
            qf[ks][2] = __float_as_uint(g_q[gr + k + 4]);
            qf[ks][3] = __float_as_uint(g_q[gr + 8 * DD + k + 4]);
        }
    }
    CP_WAIT0();
    __syncthreads();

    const int ntv = min(16, max(0, (q0 + 64 - wn * 128) / 8));

    float sacc[16][4];
    #pragma unroll
    for (int nt = 0; nt < 16; nt++)
        #pragma unroll
        for (int i = 0; i < 4; i++) sacc[nt][i] = 0.f;

    #pragma unroll
    for (int nt = 0; nt < 16; nt++) {
        if (nt >= ntv) break;
        const uint32_t* kp = sK + (wn * 128 + nt * 8 + lr) * SK_STRIDE;
        #pragma unroll
        for (int ks = 0; ks < 8; ks++) {
            uint32_t bfr[2];
            bfr[0] = kp[ks * 8 + lc];
            bfr[1] = kp[ks * 8 + lc + 4];
            mma_tf32_16n8k8(sacc[nt], qf[ks], bfr);
        }
    }

    const int row_g0 = q0 + wm * 16 + lr;
    float mrow[2] = {-INFINITY, -INFINITY};
    #pragma unroll
    for (int nt = 0; nt < 16; nt++) {
        if (nt >= ntv) break;
        #pragma unroll
        for (int i = 0; i < 4; i++) {
            int col = wn * 128 + nt * 8 + 2 * lc + (i & 1);
            int row = row_g0 + ((i >> 1) << 3);
            float v = sacc[nt][i] * 0.03125f;
            v = (col <= row) ? v : -INFINITY;
            sacc[nt][i] = v;
            if (i < 2) mrow[0] = fmaxf(mrow[0], v);
            else       mrow[1] = fmaxf(mrow[1], v);
        }
    }
    #pragma unroll
    for (int off = 1; off <= 2; off <<= 1) {
        mrow[0] = fmaxf(mrow[0], __shfl_xor_sync(0xFFFFFFFF, mrow[0], off));
        mrow[1] = fmaxf(mrow[1], __shfl_xor_sync(0xFFFFFFFF, mrow[1], off));
    }
    if (lc == 0) {
        sRed[wn * 64 + wm * 16 + lr]     = mrow[0];
        sRed[wn * 64 + wm * 16 + lr + 8] = mrow[1];
    }
    __syncthreads();

    float gm0 = fmaxf(sRed[wm * 16 + lr],     sRed[64 + wm * 16 + lr]);
    float gm1 = fmaxf(sRed[wm * 16 + lr + 8], sRed[64 + wm * 16 + lr + 8]);

    float srow[2] = {0.f, 0.f};
    #pragma unroll
    for (int nt = 0; nt < 16; nt++) {
        if (nt >= ntv) break;
        float e0 = __expf(sacc[nt][0] - gm0);
        float e1 = __expf(sacc[nt][1] - gm0);
        float e2 = __expf(sacc[nt][2] - gm1);
        float e3 = __expf(sacc[nt][3] - gm1);
        srow[0] += e0 + e1;
        srow[1] += e2 + e3;
        uint32_t* p0 = sP + (wm * 16 + lr) * SP_STRIDE2 + wn * 128 + nt * 8 + 2 * lc;
        *(uint2*)p0 = make_uint2(f32_to_tf32(e0), f32_to_tf32(e1));
        uint32_t* p1 = p0 + 8 * SP_STRIDE2;
        *(uint2*)p1 = make_uint2(f32_to_tf32(e2), f32_to_tf32(e3));
    }
    #pragma unroll
    for (int off = 1; off <= 2; off <<= 1) {
        srow[0] += __shfl_xor_sync(0xFFFFFFFF, srow[0], off);
        srow[1] += __shfl_xor_sync(0xFFFFFFFF, srow[1], off);
    }
    if (lc == 0) {
        sRed[128 + wn * 64 + wm * 16 + lr]     = srow[0];
        sRed[128 + wn * 64 + wm * 16 + lr + 8] = srow[1];
    }
    __syncthreads();

    const float inv0 = 1.f / (sRed[128 + wm * 16 + lr] +
                              sRed[128 + 64 + wm * 16 + lr]);
    const float inv1 = 1.f / (sRed[128 + wm * 16 + lr + 8] +
                              sRed[128 + 64 + wm * 16 + lr + 8]);

    float oacc[8][4];
    #pragma unroll
    for (int nt = 0; nt < 8; nt++)
        #pragma unroll
        for (int i = 0; i < 4; i++) oacc[nt][i] = 0.f;

    for (int ks = 0; ks < ntv; ks++) {
        uint32_t af[4];
        const uint32_t* ap = sP + (wm * 16 + lr) * SP_STRIDE2 + wn * 128 + ks * 8;
        af[0] = ap[lc];
        af[1] = ap[8 * SP_STRIDE2 + lc];
        af[2] = ap[lc + 4];
        af[3] = ap[8 * SP_STRIDE2 + lc + 4];
        const uint32_t* vp = sV + (wn * 128 + ks * 8 + lc) * SV_STRIDE;
        #pragma unroll
        for (int nt = 0; nt < 8; nt++) {
            uint32_t bfr[2];
            bfr[0] = vp[nt * 8 + lr];
            bfr[1] = vp[4 * SV_STRIDE + nt * 8 + lr];
            mma_tf32_16n8k8(oacc[nt], af, bfr);
        }
    }
    __syncthreads();

    if (wn == 0) {
        #pragma unroll
        for (int nt = 0; nt < 8; nt++) {
            float* o0 = sO + (wm * 16 + lr) * SO_STRIDE + nt * 8 + 2 * lc;
            *(float2*)o0 = make_float2(oacc[nt][0], oacc[nt][1]);
            float* o1 = o0 + 8 * SO_STRIDE;
            *(float2*)o1 = make_float2(oacc[nt][2], oacc[nt][3]);
        }
    }
    __syncthreads();
    if (wn == 1) {
        const size_t orow = (size_t)(bb * TT + q0 + wm * 16 + lr) * DD;
        #pragma unroll
        for (int nt = 0; nt < 8; nt++) {
            const float* o0 = sO + (wm * 16 + lr) * SO_STRIDE + nt * 8 + 2 * lc;
            const float* o1 = o0 + 8 * SO_STRIDE;
            float2 r0 = make_float2((oacc[nt][0] + o0[0]) * inv0,
                                    (oacc[nt][1] + o0[1]) * inv0);
            float2 r1 = make_float2((oacc[nt][2] + o1[0]) * inv1,
                                    (oacc[nt][3] + o1[1]) * inv1);
            *(float2*)&out[orow + nt * 8 + 2 * lc] = r0;
            *(float2*)&out[orow + 8 * DD + nt * 8 + 2 * lc] = r1;
        }
    }
}

// ---------------------------------------------------------------------------
extern "C" void kernel_launch(void* const* d_in, const int* in_sizes, int n_in,
                              void* d_out, int out_size)
{
    (void)in_sizes; (void)n_in; (void)out_size;
    const float* x  = (const float*)d_in[0];
    const float* Wq = (const float*)d_in[1];
    const float* Wk = (const float*)d_in[2];
    const float* Wv = (const float*)d_in[3];
    float* out = (float*)d_out;

    cudaFuncSetAttribute(qkv_mma_kernel,
                         cudaFuncAttributeMaxDynamicSharedMemorySize, QKV_SMEM);
    cudaFuncSetAttribute(attn_kernel,
                         cudaFuncAttributeMaxDynamicSharedMemorySize, ATT_SMEM);

    transpose_w_kernel<<<192, 256>>>(Wq, Wk, Wv);
    qkv_mma_kernel<<<BT / 128, 256, QKV_SMEM>>>(x);
    attn_kernel<<<dim3(4, BB), 256, ATT_SMEM>>>(out);
}

// round 8
// speedup vs baseline: 1.6266x; 1.4007x over previous
#include <cuda_runtime.h>
#include <cuda_fp16.h>
#include <math.h>
#include <cstdint>

#define BB 256
#define TT 256
#define CC 1024
#define DD 64
#define BT (BB*TT)

// Scratch: Q, K, V as half (8 MB each) + transposed W as half (384 KB)
__device__ __half g_qh[BT*DD];
__device__ __half g_kh[BT*DD];
__device__ __half g_vh[BT*DD];
__device__ __half g_wth[192*1024];   // K-major: rows 0-63 Wq^T, 64-127 Wk^T, 128-191 Wv^T

// ===================== PTX helpers (sm_80+ PTX, ok on compute_103) =========
__device__ __forceinline__ void mma_f16_16n8k16(
    float d[4], const uint32_t a[4], const uint32_t b[2])
{
    asm volatile(
        "mma.sync.aligned.m16n8k16.row.col.f32.f16.f16.f32 "
        "{%0,%1,%2,%3}, {%4,%5,%6,%7}, {%8,%9}, {%0,%1,%2,%3};"
        : "+f"(d[0]), "+f"(d[1]), "+f"(d[2]), "+f"(d[3])
        : "r"(a[0]), "r"(a[1]), "r"(a[2]), "r"(a[3]),
          "r"(b[0]), "r"(b[1]));
}

__device__ __forceinline__ void ldmatrix_x4(uint32_t r[4], uint32_t addr) {
    asm volatile("ldmatrix.sync.aligned.m8n8.x4.shared.b16 {%0,%1,%2,%3}, [%4];"
        : "=r"(r[0]), "=r"(r[1]), "=r"(r[2]), "=r"(r[3]) : "r"(addr));
}

__device__ __forceinline__ void ldmatrix_x4_trans(uint32_t r[4], uint32_t addr) {
    asm volatile("ldmatrix.sync.aligned.m8n8.x4.trans.shared.b16 {%0,%1,%2,%3}, [%4];"
        : "=r"(r[0]), "=r"(r[1]), "=r"(r[2]), "=r"(r[3]) : "r"(addr));
}

__device__ __forceinline__ void cp_async16(uint32_t dst, const void* src) {
    asm volatile("cp.async.cg.shared.global [%0], [%1], 16;"
        :: "r"(dst), "l"(src) : "memory");
}
#define CP_COMMIT() asm volatile("cp.async.commit_group;" ::: "memory")
#define CP_WAIT1()  asm volatile("cp.async.wait_group 1;" ::: "memory")
#define CP_WAIT0()  asm volatile("cp.async.wait_group 0;" ::: "memory")

__device__ __forceinline__ uint32_t smem_u32(const void* p) {
    uint32_t a;
    asm("{ .reg .u64 t; cvta.to.shared.u64 t, %1; cvt.u32.u64 %0, t; }"
        : "=r"(a) : "l"(p));
    return a;
}

__device__ __forceinline__ uint32_t pack_h2(float a, float b) {
    half2 h = __floats2half2_rn(a, b);
    return *(uint32_t*)&h;
}

// ===================== Kernel 0: transpose W into K-major half =============
__global__ __launch_bounds__(256) void transpose_w_kernel(
    const float* __restrict__ Wq, const float* __restrict__ Wk,
    const float* __restrict__ Wv)
{
    int n = blockIdx.x;                                 // 0..191
    const float* W = (n < 64) ? Wq : ((n < 128) ? Wk : Wv);
    int col = n & 63;
    for (int k = threadIdx.x; k < 1024; k += 256)
        g_wth[(size_t)n * 1024 + k] = __float2half_rn(W[(size_t)k * 64 + col]);
}

// ===================== Kernel A: QKV via fp16 mma ==========================
// 512 CTAs x 256 thr (8 warps = 2 M x 4 N). CTA tile 128x192, warp 64x48.
// 32 K-chunks of 32. A (x): LDG + cvt.rn half + STS. B (g_wth): cp.async.
// Smem rows: 32 halves data, stride 40 halves (80B = 5x16B, odd -> ldmatrix
// conflict-free).

#define STRH 40
#define QA_BYTES (128*STRH*2)                  // 10240
#define QB_OFF   QA_BYTES
#define QCHUNK   (QA_BYTES + 192*STRH*2)       // 25600
#define QKV_SMEM (2*QCHUNK)                    // 51200

__global__ __launch_bounds__(256) void qkv_mma_kernel(const float* __restrict__ x)
{
    extern __shared__ __half smh[];
    const uint32_t sbase = smem_u32(smh);
    const int tid    = threadIdx.x;
    const int lane   = tid & 31;
    const int wid    = tid >> 5;
    const int warp_m = wid >> 2;       // 0..1
    const int warp_n = wid & 3;        // 0..3
    const int row0   = blockIdx.x * 128;

    const int lr = lane >> 2;
    const int lc = lane & 3;

    float acc[4][6][4];
    #pragma unroll
    for (int mt = 0; mt < 4; mt++)
        #pragma unroll
        for (int nt = 0; nt < 6; nt++)
            #pragma unroll
            for (int i = 0; i < 4; i++) acc[mt][nt][i] = 0.f;

    // A staging: thread -> (row = tid>>1, half-range = (tid&1)*16)
    const int ar   = tid >> 1;         // 0..127
    const int aseg = tid & 1;

    float4 ra[4];
    auto ldg_a = [&](int c) {
        const float* src = &x[(size_t)(row0 + ar) * CC + c * 32 + aseg * 16];
        #pragma unroll
        for (int l = 0; l < 4; l++) ra[l] = *(const float4*)(src + l * 4);
    };
    auto sts_a = [&](uint32_t bufoff) {
        char* dst = (char*)smh + bufoff + ((uint32_t)(ar * STRH + aseg * 16)) * 2;
        uint4 u0 = make_uint4(pack_h2(ra[0].x, ra[0].y), pack_h2(ra[0].z, ra[0].w),
                              pack_h2(ra[1].x, ra[1].y), pack_h2(ra[1].z, ra[1].w));
        uint4 u1 = make_uint4(pack_h2(ra[2].x, ra[2].y), pack_h2(ra[2].z, ra[2].w),
                              pack_h2(ra[3].x, ra[3].y), pack_h2(ra[3].z, ra[3].w));
        *(uint4*)dst = u0;
        *(uint4*)(dst + 16) = u1;
    };
    auto cp_b = [&](int c, uint32_t bufoff) {
        #pragma unroll
        for (int l = 0; l < 3; l++) {
            int idx = tid + l * 256;           // 0..767
            int n   = idx >> 2;                // 0..191
            int sg  = idx & 3;                 // 16B segs (8 halves)
            cp_async16(sbase + bufoff + QB_OFF + (uint32_t)(n * STRH + sg * 8) * 2,
                       &g_wth[(size_t)n * 1024 + c * 32 + sg * 8]);
        }
    };

    // ldmatrix base offsets (bytes within a buffer)
    const uint32_t aoff =
        ((uint32_t)(warp_m * 64 + (lane & 7) + ((lane >> 3) & 1) * 8) * STRH
         + ((lane >> 4) & 1) * 8) * 2;
    const uint32_t boff = QB_OFF +
        ((uint32_t)(warp_n * 48 + (lane & 7) + ((lane >> 4) & 1) * 8) * STRH
         + ((lane >> 3) & 1) * 8) * 2;

    // prologue
    ldg_a(0); sts_a(0);
    cp_b(0, 0);        CP_COMMIT();
    cp_b(1, QCHUNK);   CP_COMMIT();
    ldg_a(1);

    for (int c = 0; c < 32; c++) {
        CP_WAIT1();
        __syncthreads();

        const uint32_t bufoff = (uint32_t)(c & 1) * QCHUNK;
        const uint32_t abase  = sbase + bufoff + aoff;
        const uint32_t bbase  = sbase + bufoff + boff;

        #pragma unroll
        for (int ks = 0; ks < 2; ks++) {
            uint32_t af[4][4];
            #pragma unroll
            for (int mt = 0; mt < 4; mt++)
                ldmatrix_x4(af[mt], abase + mt * (16 * STRH * 2) + ks * 32);
            uint32_t bf[12];
            #pragma unroll
            for (int j = 0; j < 3; j++)
                ldmatrix_x4(&bf[j * 4], bbase + j * (16 * STRH * 2) + ks * 32);
            #pragma unroll
            for (int mt = 0; mt < 4; mt++)
                #pragma unroll
                for (int nt = 0; nt < 6; nt++)
                    mma_f16_16n8k16(acc[mt][nt], af[mt],
                                    &bf[(nt >> 1) * 4 + (nt & 1) * 2]);
        }

        if (c + 1 < 32) {
            sts_a((uint32_t)((c + 1) & 1) * QCHUNK);
            if (c + 2 < 32) ldg_a(c + 2);
        }
        __syncthreads();

        if (c + 2 < 32) cp_b(c + 2, bufoff);
        CP_COMMIT();
    }

    // epilogue: convert to half (rn), scatter to g_qh / g_kh / g_vh
    #pragma unroll
    for (int mt = 0; mt < 4; mt++) {
        int rg = row0 + warp_m * 64 + mt * 16 + lr;
        #pragma unroll
        for (int nt = 0; nt < 6; nt++) {
            int ng = warp_n * 48 + nt * 8 + lc * 2;
            int m  = ng >> 6;
            int d  = ng & 63;
            __half* base = (m == 0) ? g_qh : (m == 1) ? g_kh : g_vh;
            *(uint32_t*)&base[(size_t)rg * DD + d] =
                pack_h2(acc[mt][nt][0], acc[mt][nt][1]);
            *(uint32_t*)&base[(size_t)(rg + 8) * DD + d] =
                pack_h2(acc[mt][nt][2], acc[mt][nt][3]);
        }
    }
}

// ===================== Kernel B: attention via fp16 mma ====================
// Grid (4, 256). 8 warps: wm = wid>>1 (16 q-rows), wn = wid&1 (128 keys).
// K/V staged as half via cp.async (causal prefix only), stride 72 halves
// (144B = 9x16B odd). P stored half2, row stride 264 halves. V fragments via
// ldmatrix.x4.trans.

#define KSTR 72
#define SKB  0
#define SVB  (256*KSTR*2)                  // 36864
#define REDB (2*256*KSTR*2)                // 73728
#define ATT_SMEM (REDB + 1024)             // 74752
#define PSTR32 132                         // P row stride in u32 (264 halves)
#define SO_STRIDE 66

__global__ __launch_bounds__(256) void attn_kernel(float* __restrict__ out)
{
    extern __shared__ __half smh[];
    const uint32_t sbase = smem_u32(smh);
    float*    sRed = (float*)((char*)smh + REDB);
    uint32_t* sP32 = (uint32_t*)smh;                 // P overlays K region
    float*    sO   = (float*)smh;                    // O overlays after P dead

    const int tid  = threadIdx.x;
    const int wid  = tid >> 5;
    const int lane = tid & 31;
    const int wm   = wid >> 1;
    const int wn   = wid & 1;
    const int lr   = lane >> 2;
    const int lc   = lane & 3;

    const int qt = blockIdx.x;
    const int bb = blockIdx.y;
    const int q0 = qt * 64;
    const int rows = q0 + 64;              // causal prefix length

    // ---- cp.async stage K, V prefix (half) ----
    const __half* kb = g_kh + (size_t)bb * TT * DD;
    const __half* vb = g_vh + (size_t)bb * TT * DD;
    for (int idx = tid; idx < rows * 8; idx += 256) {
        int s  = idx >> 3;
        int sg = idx & 7;
        cp_async16(sbase + SKB + (uint32_t)(s * KSTR + sg * 8) * 2,
                   &kb[s * DD + sg * 8]);
        cp_async16(sbase + SVB + (uint32_t)(s * KSTR + sg * 8) * 2,
                   &vb[s * DD + sg * 8]);
    }
    CP_COMMIT();

    // ---- Q fragments from gmem (half2 loads) ----
    uint32_t qf[4][4];
    {
        const uint32_t* q32 =
            (const uint32_t*)(g_qh + (size_t)(bb * TT + q0 + wm * 16 + lr) * DD);
        const uint32_t* q32b = q32 + 8 * 32;          // row + 8
        #pragma unroll
        for (int ks = 0; ks < 4; ks++) {
            qf[ks][0] = q32 [ks * 8 + lc];
            qf[ks][1] = q32b[ks * 8 + lc];
            qf[ks][2] = q32 [ks * 8 + lc + 4];
            qf[ks][3] = q32b[ks * 8 + lc + 4];
        }
    }
    CP_WAIT0();
    __syncthreads();

    const int ntv = min(16, max(0, (q0 + 64 - wn * 128) / 8));  // 8-key tiles
    const int ng2 = ntv >> 1;

    // ---- QK^T ----
    float sacc[16][4];
    #pragma unroll
    for (int nt = 0; nt < 16; nt++)
        #pragma unroll
        for (int i = 0; i < 4; i++) sacc[nt][i] = 0.f;

    {
        const uint32_t kbase = sbase + SKB +
            ((uint32_t)(wn * 128 + (lane & 7) + ((lane >> 4) & 1) * 8) * KSTR
             + ((lane >> 3) & 1) * 8) * 2;
        #pragma unroll
        for (int g = 0; g < 8; g++) {
            if (g >= ng2) break;
            #pragma unroll
            for (int ks = 0; ks < 4; ks++) {
                uint32_t bf[4];
                ldmatrix_x4(bf, kbase + g * (16 * KSTR * 2) + ks * 32);
                mma_f16_16n8k16(sacc[2*g],     qf[ks], &bf[0]);
                mma_f16_16n8k16(sacc[2*g + 1], qf[ks], &bf[2]);
            }
        }
    }

    // ---- scale + causal mask + row max ----
    const int row_g0 = q0 + wm * 16 + lr;
    float mrow[2] = {-INFINITY, -INFINITY};
    #pragma unroll
    for (int nt = 0; nt < 16; nt++) {
        if (nt >= ntv) break;
        #pragma unroll
        for (int i = 0; i < 4; i++) {
            int col = wn * 128 + nt * 8 + 2 * lc + (i & 1);
            int row = row_g0 + ((i >> 1) << 3);
            float v = sacc[nt][i] * 0.03125f;
            v = (col <= row) ? v : -INFINITY;
            sacc[nt][i] = v;
            if (i < 2) mrow[0] = fmaxf(mrow[0], v);
            else       mrow[1] = fmaxf(mrow[1], v);
        }
    }
    #pragma unroll
    for (int off = 1; off <= 2; off <<= 1) {
        mrow[0] = fmaxf(mrow[0], __shfl_xor_sync(0xFFFFFFFF, mrow[0], off));
        mrow[1] = fmaxf(mrow[1], __shfl_xor_sync(0xFFFFFFFF, mrow[1], off));
    }
    if (lc == 0) {
        sRed[wn * 64 + wm * 16 + lr]     = mrow[0];
        sRed[wn * 64 + wm * 16 + lr + 8] = mrow[1];
    }
    __syncthreads();   // also: all warps done reading sK -> P may overwrite

    float gm0 = fmaxf(sRed[wm * 16 + lr],     sRed[64 + wm * 16 + lr]);
    float gm1 = fmaxf(sRed[wm * 16 + lr + 8], sRed[64 + wm * 16 + lr + 8]);

    // ---- exp, store P (half2), partial sums ----
    float srow[2] = {0.f, 0.f};
    #pragma unroll
    for (int nt = 0; nt < 16; nt++) {
        if (nt >= ntv) break;
        float e0 = __expf(sacc[nt][0] - gm0);
        float e1 = __expf(sacc[nt][1] - gm0);
        float e2 = __expf(sacc[nt][2] - gm1);
        float e3 = __expf(sacc[nt][3] - gm1);
        srow[0] += e0 + e1;
        srow[1] += e2 + e3;
        uint32_t* p0 = sP32 + (wm * 16 + lr) * PSTR32 + wn * 64 + nt * 4 + lc;
        p0[0]            = pack_h2(e0, e1);
        p0[8 * PSTR32]   = pack_h2(e2, e3);
    }
    #pragma unroll
    for (int off = 1; off <= 2; off <<= 1) {
        srow[0] += __shfl_xor_sync(0xFFFFFFFF, srow[0], off);
        srow[1] += __shfl_xor_sync(0xFFFFFFFF, srow[1], off);
    }
    if (lc == 0) {
        sRed[128 + wn * 64 + wm * 16 + lr]     = srow[0];
        sRed[128 + wn * 64 + wm * 16 + lr + 8] = srow[1];
    }
    __syncthreads();

    const float inv0 = 1.f / (sRed[128 + wm * 16 + lr] +
                              sRed[128 + 64 + wm * 16 + lr]);
    const float inv1 = 1.f / (sRed[128 + wm * 16 + lr + 8] +
                              sRed[128 + 64 + wm * 16 + lr + 8]);

    // ---- PV: k-steps of 16 keys; V fragments via ldmatrix.trans ----
    float oacc[8][4];
    #pragma unroll
    for (int nt = 0; nt < 8; nt++)
        #pragma unroll
        for (int i = 0; i < 4; i++) oacc[nt][i] = 0.f;

    {
        const uint32_t vbase = sbase + SVB +
            ((uint32_t)(wn * 128 + (lane & 7) + ((lane >> 3) & 1) * 8) * KSTR
             + ((lane >> 4) & 1) * 8) * 2;
        for (int ks2 = 0; ks2 < ng2; ks2++) {
            uint32_t af[4];
            const uint32_t* ap = sP32 + (wm * 16 + lr) * PSTR32 + wn * 64 + ks2 * 8;
            af[0] = ap[lc];
            af[1] = ap[8 * PSTR32 + lc];
            af[2] = ap[lc + 4];
            af[3] = ap[8 * PSTR32 + lc + 4];
            #pragma unroll
            for (int pr = 0; pr < 4; pr++) {
                uint32_t bf[4];
                ldmatrix_x4_trans(bf, vbase + ks2 * (16 * KSTR * 2) + pr * 32);
                mma_f16_16n8k16(oacc[2*pr],     af, &bf[0]);
                mma_f16_16n8k16(oacc[2*pr + 1], af, &bf[2]);
            }
        }
    }
    __syncthreads();   // everyone done with P/V regions

    // ---- cross-warp_n reduction + output ----
    if (wn == 0) {
        #pragma unroll
        for (int nt = 0; nt < 8; nt++) {
            float* o0 = sO + (wm * 16 + lr) * SO_STRIDE + nt * 8 + 2 * lc;
            *(float2*)o0 = make_float2(oacc[nt][0], oacc[nt][1]);
            float* o1 = o0 + 8 * SO_STRIDE;
            *(float2*)o1 = make_float2(oacc[nt][2], oacc[nt][3]);
        }
    }
    __syncthreads();
    if (wn == 1) {
        const size_t orow = (size_t)(bb * TT + q0 + wm * 16 + lr) * DD;
        #pragma unroll
        for (int nt = 0; nt < 8; nt++) {
            const float* o0 = sO + (wm * 16 + lr) * SO_STRIDE + nt * 8 + 2 * lc;
            const float* o1 = o0 + 8 * SO_STRIDE;
            float2 r0 = make_float2((oacc[nt][0] + o0[0]) * inv0,
                                    (oacc[nt][1] + o0[1]) * inv0);
            float2 r1 = make_float2((oacc[nt][2] + o1[0]) * inv1,
                                    (oacc[nt][3] + o1[1]) * inv1);
            *(float2*)&out[orow + nt * 8 + 2 * lc] = r0;
            *(float2*)&out[orow + 8 * DD + nt * 8 + 2 * lc] = r1;
        }
    }
}

// ---------------------------------------------------------------------------
extern "C" void kernel_launch(void* const* d_in, const int* in_sizes, int n_in,
                              void* d_out, int out_size)
{
    (void)in_sizes; (void)n_in; (void)out_size;
    const float* x  = (const float*)d_in[0];
    const float* Wq = (const float*)d_in[1];
    const float* Wk = (const float*)d_in[2];
    const float* Wv = (const float*)d_in[3];
    float* out = (float*)d_out;

    cudaFuncSetAttribute(qkv_mma_kernel,
                         cudaFuncAttributeMaxDynamicSharedMemorySize, QKV_SMEM);
    cudaFuncSetAttribute(attn_kernel,
                         cudaFuncAttributeMaxDynamicSharedMemorySize, ATT_SMEM);

    transpose_w_kernel<<<192, 256>>>(Wq, Wk, Wv);
    qkv_mma_kernel<<<BT / 128, 256, QKV_SMEM>>>(x);
    attn_kernel<<<dim3(4, BB), 256, ATT_SMEM>>>(out);
}

// round 9
// speedup vs baseline: 1.9369x; 1.1908x over previous
#include <cuda_runtime.h>
#include <cuda_fp16.h>
#include <math.h>
#include <cstdint>

#define BB 256
#define TT 256
#define CC 1024
#define DD 64
#define BT (BB*TT)

// Scratch: Q, K, V as half (8 MB each) + transposed W as half (384 KB)
__device__ __half g_qh[BT*DD];
__device__ __half g_kh[BT*DD];
__device__ __half g_vh[BT*DD];
__device__ __half g_wth[192*1024];   // K-major: rows 0-63 Wq^T, 64-127 Wk^T, 128-191 Wv^T

// ===================== PTX helpers (sm_80+ PTX, ok on compute_103) =========
__device__ __forceinline__ void mma_f16_16n8k16(
    float d[4], const uint32_t a[4], const uint32_t b[2])
{
    asm volatile(
        "mma.sync.aligned.m16n8k16.row.col.f32.f16.f16.f32 "
        "{%0,%1,%2,%3}, {%4,%5,%6,%7}, {%8,%9}, {%0,%1,%2,%3};"
        : "+f"(d[0]), "+f"(d[1]), "+f"(d[2]), "+f"(d[3])
        : "r"(a[0]), "r"(a[1]), "r"(a[2]), "r"(a[3]),
          "r"(b[0]), "r"(b[1]));
}

__device__ __forceinline__ void ldmatrix_x4(uint32_t r[4], uint32_t addr) {
    asm volatile("ldmatrix.sync.aligned.m8n8.x4.shared.b16 {%0,%1,%2,%3}, [%4];"
        : "=r"(r[0]), "=r"(r[1]), "=r"(r[2]), "=r"(r[3]) : "r"(addr));
}

__device__ __forceinline__ void ldmatrix_x4_trans(uint32_t r[4], uint32_t addr) {
    asm volatile("ldmatrix.sync.aligned.m8n8.x4.trans.shared.b16 {%0,%1,%2,%3}, [%4];"
        : "=r"(r[0]), "=r"(r[1]), "=r"(r[2]), "=r"(r[3]) : "r"(addr));
}

__device__ __forceinline__ void cp_async16(uint32_t dst, const void* src) {
    asm volatile("cp.async.cg.shared.global [%0], [%1], 16;"
        :: "r"(dst), "l"(src) : "memory");
}
#define CP_COMMIT() asm volatile("cp.async.commit_group;" ::: "memory")
#define CP_WAIT1()  asm volatile("cp.async.wait_group 1;" ::: "memory")
#define CP_WAIT0()  asm volatile("cp.async.wait_group 0;" ::: "memory")

__device__ __forceinline__ uint32_t smem_u32(const void* p) {
    uint32_t a;
    asm("{ .reg .u64 t; cvta.to.shared.u64 t, %1; cvt.u32.u64 %0, t; }"
        : "=r"(a) : "l"(p));
    return a;
}

__device__ __forceinline__ uint32_t pack_h2(float a, float b) {
    half2 h = __floats2half2_rn(a, b);
    return *(uint32_t*)&h;
}

// ===================== Kernel 0: coalesced tile-transpose of W =============
// Grid 48 = 3 matrices x 16 k-tiles. Block 256. Tile 64k x 64n via smem.
__global__ __launch_bounds__(256) void transpose_w_kernel(
    const float* __restrict__ Wq, const float* __restrict__ Wk,
    const float* __restrict__ Wv)
{
    __shared__ float tile[64][65];
    const int m  = blockIdx.x >> 4;          // 0..2
    const int kt = blockIdx.x & 15;          // 0..15
    const float* W = (m == 0) ? Wq : (m == 1) ? Wk : Wv;

    const int r   = threadIdx.x >> 2;        // 0..63
    const int seg = threadIdx.x & 3;         // 0..3 (16 floats each)
    #pragma unroll
    for (int l = 0; l < 4; l++) {
        float4 v = *(const float4*)&W[(size_t)(kt * 64 + r) * 64 + seg * 16 + l * 4];
        tile[r][seg * 16 + l * 4 + 0] = v.x;
        tile[r][seg * 16 + l * 4 + 1] = v.y;
        tile[r][seg * 16 + l * 4 + 2] = v.z;
        tile[r][seg * 16 + l * 4 + 3] = v.w;
    }
    __syncthreads();

    const int n = r;                          // output row (head col)
    uint32_t u[8];
    #pragma unroll
    for (int i = 0; i < 8; i++)
        u[i] = pack_h2(tile[seg * 16 + 2 * i][n], tile[seg * 16 + 2 * i + 1][n]);
    char* dst = (char*)&g_wth[(size_t)(m * 64 + n) * 1024 + kt * 64 + seg * 16];
    *(uint4*)dst        = make_uint4(u[0], u[1], u[2], u[3]);
    *(uint4*)(dst + 16) = make_uint4(u[4], u[5], u[6], u[7]);
}

// ===================== Kernel A: QKV via fp16 mma ==========================
// 1024 CTAs x 256 thr (8 warps = 2 M x 4 N), 2 CTAs/SM. CTA tile 64x192,
// warp tile 32x48. 16 K-chunks of 64. A (x): LDG + cvt + STS. B: cp.async.
// Smem rows: 64 halves data, stride 72 halves (144B = 9x16B -> conflict-free).

#define STRH 72
#define QA_BYTES (64*STRH*2)                   // 9216
#define QB_OFF   QA_BYTES
#define QCHUNK   (QA_BYTES + 192*STRH*2)       // 36864
#define QKV_SMEM (2*QCHUNK)                    // 73728

__global__ __launch_bounds__(256, 2) void qkv_mma_kernel(const float* __restrict__ x)
{
    extern __shared__ __half smh[];
    const uint32_t sbase = smem_u32(smh);
    const int tid    = threadIdx.x;
    const int lane   = tid & 31;
    const int wid    = tid >> 5;
    const int warp_m = wid >> 2;       // 0..1 (32 rows each)
    const int warp_n = wid & 3;        // 0..3 (48 cols each)
    const int row0   = blockIdx.x * 64;

    const int lr = lane >> 2;
    const int lc = lane & 3;

    float acc[2][6][4];
    #pragma unroll
    for (int mt = 0; mt < 2; mt++)
        #pragma unroll
        for (int nt = 0; nt < 6; nt++)
            #pragma unroll
            for (int i = 0; i < 4; i++) acc[mt][nt][i] = 0.f;

    // A staging: thread -> row = tid>>2 (0..63), 16-float seg = tid&3
    const int ar   = tid >> 2;
    const int aseg = tid & 3;

    float4 ra[4];
    auto ldg_a = [&](int c) {
        const float* src = &x[(size_t)(row0 + ar) * CC + c * 64 + aseg * 16];
        #pragma unroll
        for (int l = 0; l < 4; l++) ra[l] = *(const float4*)(src + l * 4);
    };
    auto sts_a = [&](uint32_t bufoff) {
        char* dst = (char*)smh + bufoff + ((uint32_t)(ar * STRH + aseg * 16)) * 2;
        uint4 u0 = make_uint4(pack_h2(ra[0].x, ra[0].y), pack_h2(ra[0].z, ra[0].w),
                              pack_h2(ra[1].x, ra[1].y), pack_h2(ra[1].z, ra[1].w));
        uint4 u1 = make_uint4(pack_h2(ra[2].x, ra[2].y), pack_h2(ra[2].z, ra[2].w),
                              pack_h2(ra[3].x, ra[3].y), pack_h2(ra[3].z, ra[3].w));
        *(uint4*)dst = u0;
        *(uint4*)(dst + 16) = u1;
    };
    auto cp_b = [&](int c, uint32_t bufoff) {
        #pragma unroll
        for (int l = 0; l < 6; l++) {
            int idx = tid + l * 256;           // 0..1535
            int n   = idx >> 3;                // 0..191
            int sg  = idx & 7;                 // 16B segs (8 halves)
            cp_async16(sbase + bufoff + QB_OFF + (uint32_t)(n * STRH + sg * 8) * 2,
                       &g_wth[(size_t)n * 1024 + c * 64 + sg * 8]);
        }
    };

    // ldmatrix base offsets (bytes within a buffer)
    const uint32_t aoff =
        ((uint32_t)(warp_m * 32 + (lane & 7) + ((lane >> 3) & 1) * 8) * STRH
         + ((lane >> 4) & 1) * 8) * 2;
    const uint32_t boff = QB_OFF +
        ((uint32_t)(warp_n * 48 + (lane & 7) + ((lane >> 4) & 1) * 8) * STRH
         + ((lane >> 3) & 1) * 8) * 2;

    // prologue
    ldg_a(0); sts_a(0);
    cp_b(0, 0);        CP_COMMIT();
    cp_b(1, QCHUNK);   CP_COMMIT();
    ldg_a(1);

    for (int c = 0; c < 16; c++) {
        CP_WAIT1();
        __syncthreads();

        const uint32_t bufoff = (uint32_t)(c & 1) * QCHUNK;
        const uint32_t abase  = sbase + bufoff + aoff;
        const uint32_t bbase  = sbase + bufoff + boff;

        #pragma unroll
        for (int ks = 0; ks < 4; ks++) {
            uint32_t af[2][4];
            #pragma unroll
            for (int mt = 0; mt < 2; mt++)
                ldmatrix_x4(af[mt], abase + mt * (16 * STRH * 2) + ks * 32);
            uint32_t bf[12];
            #pragma unroll
            for (int j = 0; j < 3; j++)
                ldmatrix_x4(&bf[j * 4], bbase + j * (16 * STRH * 2) + ks * 32);
            #pragma unroll
            for (int mt = 0; mt < 2; mt++)
                #pragma unroll
                for (int nt = 0; nt < 6; nt++)
                    mma_f16_16n8k16(acc[mt][nt], af[mt],
                                    &bf[(nt >> 1) * 4 + (nt & 1) * 2]);
        }

        if (c + 1 < 16) {
            sts_a((uint32_t)((c + 1) & 1) * QCHUNK);
            if (c + 2 < 16) ldg_a(c + 2);
        }
        __syncthreads();

        if (c + 2 < 16) cp_b(c + 2, bufoff);
        CP_COMMIT();
    }

    // epilogue: convert to half (rn), scatter to g_qh / g_kh / g_vh
    #pragma unroll
    for (int mt = 0; mt < 2; mt++) {
        int rg = row0 + warp_m * 32 + mt * 16 + lr;
        #pragma unroll
        for (int nt = 0; nt < 6; nt++) {
            int ng = warp_n * 48 + nt * 8 + lc * 2;
            int m  = ng >> 6;
            int d  = ng & 63;
            __half* base = (m == 0) ? g_qh : (m == 1) ? g_kh : g_vh;
            *(uint32_t*)&base[(size_t)rg * DD + d] =
                pack_h2(acc[mt][nt][0], acc[mt][nt][1]);
            *(uint32_t*)&base[(size_t)(rg + 8) * DD + d] =
                pack_h2(acc[mt][nt][2], acc[mt][nt][3]);
        }
    }
}

// ===================== Kernel B: attention via fp16 mma (unchanged R8) =====
#define KSTR 72
#define SKB  0
#define SVB  (256*KSTR*2)                  // 36864
#define REDB (2*256*KSTR*2)                // 73728
#define ATT_SMEM (REDB + 1024)             // 74752
#define PSTR32 132                         // P row stride in u32 (264 halves)
#define SO_STRIDE 66

__global__ __launch_bounds__(256) void attn_kernel(float* __restrict__ out)
{
    extern __shared__ __half smh[];
    const uint32_t sbase = smem_u32(smh);
    float*    sRed = (float*)((char*)smh + REDB);
    uint32_t* sP32 = (uint32_t*)smh;                 // P overlays K region
    float*    sO   = (float*)smh;                    // O overlays after P dead

    const int tid  = threadIdx.x;
    const int wid  = tid >> 5;
    const int lane = tid & 31;
    const int wm   = wid >> 1;
    const int wn   = wid & 1;
    const int lr   = lane >> 2;
    const int lc   = lane & 3;

    const int qt = blockIdx.x;
    const int bb = blockIdx.y;
    const int q0 = qt * 64;
    const int rows = q0 + 64;              // causal prefix length

    const __half* kb = g_kh + (size_t)bb * TT * DD;
    const __half* vb = g_vh + (size_t)bb * TT * DD;
    for (int idx = tid; idx < rows * 8; idx += 256) {
        int s  = idx >> 3;
        int sg = idx & 7;
        cp_async16(sbase + SKB + (uint32_t)(s * KSTR + sg * 8) * 2,
                   &kb[s * DD + sg * 8]);
        cp_async16(sbase + SVB + (uint32_t)(s * KSTR + sg * 8) * 2,
                   &vb[s * DD + sg * 8]);
    }
    CP_COMMIT();

    uint32_t qf[4][4];
    {
        const uint32_t* q32 =
            (const uint32_t*)(g_qh + (size_t)(bb * TT + q0 + wm * 16 + lr) * DD);
        const uint32_t* q32b = q32 + 8 * 32;          // row + 8
        #pragma unroll
        for (int ks = 0; ks < 4; ks++) {
            qf[ks][0] = q32 [ks * 8 + lc];
            qf[ks][1] = q32b[ks * 8 + lc];
            qf[ks][2] = q32 [ks * 8 + lc + 4];
            qf[ks][3] = q32b[ks * 8 + lc + 4];
        }
    }
    CP_WAIT0();
    __syncthreads();

    const int ntv = min(16, max(0, (q0 + 64 - wn * 128) / 8));  // 8-key tiles
    const int ng2 = ntv >> 1;

    float sacc[16][4];
    #pragma unroll
    for (int nt = 0; nt < 16; nt++)
        #pragma unroll
        for (int i = 0; i < 4; i++) sacc[nt][i] = 0.f;

    {
        const uint32_t kbase = sbase + SKB +
            ((uint32_t)(wn * 128 + (lane & 7) + ((lane >> 4) & 1) * 8) * KSTR
             + ((lane >> 3) & 1) * 8) * 2;
        #pragma unroll
        for (int g = 0; g < 8; g++) {
            if (g >= ng2) break;
            #pragma unroll
            for (int ks = 0; ks < 4; ks++) {
                uint32_t bf[4];
                ldmatrix_x4(bf, kbase + g * (16 * KSTR * 2) + ks * 32);
                mma_f16_16n8k16(sacc[2*g],     qf[ks], &bf[0]);
                mma_f16_16n8k16(sacc[2*g + 1], qf[ks], &bf[2]);
            }
        }
    }

    const int row_g0 = q0 + wm * 16 + lr;
    float mrow[2] = {-INFINITY, -INFINITY};
    #pragma unroll
    for (int nt = 0; nt < 16; nt++) {
        if (nt >= ntv) break;
        #pragma unroll
        for (int i = 0; i < 4; i++) {
            int col = wn * 128 + nt * 8 + 2 * lc + (i & 1);
            int row = row_g0 + ((i >> 1) << 3);
            float v = sacc[nt][i] * 0.03125f;
            v = (col <= row) ? v : -INFINITY;
            sacc[nt][i] = v;
            if (i < 2) mrow[0] = fmaxf(mrow[0], v);
            else       mrow[1] = fmaxf(mrow[1], v);
        }
    }
    #pragma unroll
    for (int off = 1; off <= 2; off <<= 1) {
        mrow[0] = fmaxf(mrow[0], __shfl_xor_sync(0xFFFFFFFF, mrow[0], off));
        mrow[1] = fmaxf(mrow[1], __shfl_xor_sync(0xFFFFFFFF, mrow[1], off));
    }
    if (lc == 0) {
        sRed[wn * 64 + wm * 16 + lr]     = mrow[0];
        sRed[wn * 64 + wm * 16 + lr + 8] = mrow[1];
    }
    __syncthreads();

    float gm0 = fmaxf(sRed[wm * 16 + lr],     sRed[64 + wm * 16 + lr]);
    float gm1 = fmaxf(sRed[wm * 16 + lr + 8], sRed[64 + wm * 16 + lr + 8]);

    float srow[2] = {0.f, 0.f};
    #pragma unroll
    for (int nt = 0; nt < 16; nt++) {
        if (nt >= ntv) break;
        float e0 = __expf(sacc[nt][0] - gm0);
        float e1 = __expf(sacc[nt][1] - gm0);
        float e2 = __expf(sacc[nt][2] - gm1);
        float e3 = __expf(sacc[nt][3] - gm1);
        srow[0] += e0 + e1;
        srow[1] += e2 + e3;
        uint32_t* p0 = sP32 + (wm * 16 + lr) * PSTR32 + wn * 64 + nt * 4 + lc;
        p0[0]            = pack_h2(e0, e1);
        p0[8 * PSTR32]   = pack_h2(e2, e3);
    }
    #pragma unroll
    for (int off = 1; off <= 2; off <<= 1) {
        srow[0] += __shfl_xor_sync(0xFFFFFFFF, srow[0], off);
        srow[1] += __shfl_xor_sync(0xFFFFFFFF, srow[1], off);
    }
    if (lc == 0) {
        sRed[128 + wn * 64 + wm * 16 + lr]     = srow[0];
        sRed[128 + wn * 64 + wm * 16 + lr + 8] = srow[1];
    }
    __syncthreads();

    const float inv0 = 1.f / (sRed[128 + wm * 16 + lr] +
                              sRed[128 + 64 + wm * 16 + lr]);
    const float inv1 = 1.f / (sRed[128 + wm * 16 + lr + 8] +
                              sRed[128 + 64 + wm * 16 + lr + 8]);

    float oacc[8][4];
    #pragma unroll
    for (int nt = 0; nt < 8; nt++)
        #pragma unroll
        for (int i = 0; i < 4; i++) oacc[nt][i] = 0.f;

    {
        const uint32_t vbase = sbase + SVB +
            ((uint32_t)(wn * 128 + (lane & 7) + ((lane >> 3) & 1) * 8) * KSTR
             + ((lane >> 4) & 1) * 8) * 2;
        for (int ks2 = 0; ks2 < ng2; ks2++) {
            uint32_t af[4];
            const uint32_t* ap = sP32 + (wm * 16 + lr) * PSTR32 + wn * 64 + ks2 * 8;
            af[0] = ap[lc];
            af[1] = ap[8 * PSTR32 + lc];
            af[2] = ap[lc + 4];
            af[3] = ap[8 * PSTR32 + lc + 4];
            #pragma unroll
            for (int pr = 0; pr < 4; pr++) {
                uint32_t bf[4];
                ldmatrix_x4_trans(bf, vbase + ks2 * (16 * KSTR * 2) + pr * 32);
                mma_f16_16n8k16(oacc[2*pr],     af, &bf[0]);
                mma_f16_16n8k16(oacc[2*pr + 1], af, &bf[2]);
            }
        }
    }
    __syncthreads();

    if (wn == 0) {
        #pragma unroll
        for (int nt = 0; nt < 8; nt++) {
            float* o0 = sO + (wm * 16 + lr) * SO_STRIDE + nt * 8 + 2 * lc;
            *(float2*)o0 = make_float2(oacc[nt][0], oacc[nt][1]);
            float* o1 = o0 + 8 * SO_STRIDE;
            *(float2*)o1 = make_float2(oacc[nt][2], oacc[nt][3]);
        }
    }
    __syncthreads();
    if (wn == 1) {
        const size_t orow = (size_t)(bb * TT + q0 + wm * 16 + lr) * DD;
        #pragma unroll
        for (int nt = 0; nt < 8; nt++) {
            const float* o0 = sO + (wm * 16 + lr) * SO_STRIDE + nt * 8 + 2 * lc;
            const float* o1 = o0 + 8 * SO_STRIDE;
            float2 r0 = make_float2((oacc[nt][0] + o0[0]) * inv0,
                                    (oacc[nt][1] + o0[1]) * inv0);
            float2 r1 = make_float2((oacc[nt][2] + o1[0]) * inv1,
                                    (oacc[nt][3] + o1[1]) * inv1);
            *(float2*)&out[orow + nt * 8 + 2 * lc] = r0;
            *(float2*)&out[orow + 8 * DD + nt * 8 + 2 * lc] = r1;
        }
    }
}

// ---------------------------------------------------------------------------
extern "C" void kernel_launch(void* const* d_in, const int* in_sizes, int n_in,
                              void* d_out, int out_size)
{
    (void)in_sizes; (void)n_in; (void)out_size;
    const float* x  = (const float*)d_in[0];
    const float* Wq = (const float*)d_in[1];
    const float* Wk = (const float*)d_in[2];
    const float* Wv = (const float*)d_in[3];
    float* out = (float*)d_out;

    cudaFuncSetAttribute(qkv_mma_kernel,
                         cudaFuncAttributeMaxDynamicSharedMemorySize, QKV_SMEM);
    cudaFuncSetAttribute(attn_kernel,
                         cudaFuncAttributeMaxDynamicSharedMemorySize, ATT_SMEM);

    transpose_w_kernel<<<48, 256>>>(Wq, Wk, Wv);
    qkv_mma_kernel<<<BT / 64, 256, QKV_SMEM>>>(x);
    attn_kernel<<<dim3(4, BB), 256, ATT_SMEM>>>(out);
}

// round 10
// speedup vs baseline: 1.9423x; 1.0028x over previous
#include <cuda_runtime.h>
#include <cuda_fp16.h>
#include <math.h>
#include <cstdint>

#define BB 256
#define TT 256
#define CC 1024
#define DD 64
#define BT (BB*TT)

// Scratch: Q, K, V as half (8 MB each) + transposed W as half (384 KB)
__device__ __half g_qh[BT*DD];
__device__ __half g_kh[BT*DD];
__device__ __half g_vh[BT*DD];
__device__ __half g_wth[192*1024];   // K-major: rows 0-63 Wq^T, 64-127 Wk^T, 128-191 Wv^T

// ===================== PTX helpers (sm_80+ PTX, ok on compute_103) =========
__device__ __forceinline__ void mma_f16_16n8k16(
    float d[4], const uint32_t a[4], const uint32_t b[2])
{
    asm volatile(
        "mma.sync.aligned.m16n8k16.row.col.f32.f16.f16.f32 "
        "{%0,%1,%2,%3}, {%4,%5,%6,%7}, {%8,%9}, {%0,%1,%2,%3};"
        : "+f"(d[0]), "+f"(d[1]), "+f"(d[2]), "+f"(d[3])
        : "r"(a[0]), "r"(a[1]), "r"(a[2]), "r"(a[3]),
          "r"(b[0]), "r"(b[1]));
}

__device__ __forceinline__ void ldmatrix_x4(uint32_t r[4], uint32_t addr) {
    asm volatile("ldmatrix.sync.aligned.m8n8.x4.shared.b16 {%0,%1,%2,%3}, [%4];"
        : "=r"(r[0]), "=r"(r[1]), "=r"(r[2]), "=r"(r[3]) : "r"(addr));
}

__device__ __forceinline__ void ldmatrix_x4_trans(uint32_t r[4], uint32_t addr) {
    asm volatile("ldmatrix.sync.aligned.m8n8.x4.trans.shared.b16 {%0,%1,%2,%3}, [%4];"
        : "=r"(r[0]), "=r"(r[1]), "=r"(r[2]), "=r"(r[3]) : "r"(addr));
}

__device__ __forceinline__ void cp_async16(uint32_t dst, const void* src) {
    asm volatile("cp.async.cg.shared.global [%0], [%1], 16;"
        :: "r"(dst), "l"(src) : "memory");
}
#define CP_COMMIT() asm volatile("cp.async.commit_group;" ::: "memory")
#define CP_WAIT1()  asm volatile("cp.async.wait_group 1;" ::: "memory")
#define CP_WAIT0()  asm volatile("cp.async.wait_group 0;" ::: "memory")

__device__ __forceinline__ uint32_t smem_u32(const void* p) {
    uint32_t a;
    asm("{ .reg .u64 t; cvta.to.shared.u64 t, %1; cvt.u32.u64 %0, t; }"
        : "=r"(a) : "l"(p));
    return a;
}

__device__ __forceinline__ uint32_t pack_h2(float a, float b) {
    half2 h = __floats2half2_rn(a, b);
    return *(uint32_t*)&h;
}

// ===================== Kernel 0: coalesced tile-transpose of W =============
__global__ __launch_bounds__(256) void transpose_w_kernel(
    const float* __restrict__ Wq, const float* __restrict__ Wk,
    const float* __restrict__ Wv)
{
    __shared__ float tile[64][65];
    const int m  = blockIdx.x >> 4;          // 0..2
    const int kt = blockIdx.x & 15;          // 0..15
    const float* W = (m == 0) ? Wq : (m == 1) ? Wk : Wv;

    const int r   = threadIdx.x >> 2;        // 0..63
    const int seg = threadIdx.x & 3;         // 0..3 (16 floats each)
    #pragma unroll
    for (int l = 0; l < 4; l++) {
        float4 v = *(const float4*)&W[(size_t)(kt * 64 + r) * 64 + seg * 16 + l * 4];
        tile[r][seg * 16 + l * 4 + 0] = v.x;
        tile[r][seg * 16 + l * 4 + 1] = v.y;
        tile[r][seg * 16 + l * 4 + 2] = v.z;
        tile[r][seg * 16 + l * 4 + 3] = v.w;
    }
    __syncthreads();

    const int n = r;
    uint32_t u[8];
    #pragma unroll
    for (int i = 0; i < 8; i++)
        u[i] = pack_h2(tile[seg * 16 + 2 * i][n], tile[seg * 16 + 2 * i + 1][n]);
    char* dst = (char*)&g_wth[(size_t)(m * 64 + n) * 1024 + kt * 64 + seg * 16];
    *(uint4*)dst        = make_uint4(u[0], u[1], u[2], u[3]);
    *(uint4*)(dst + 16) = make_uint4(u[4], u[5], u[6], u[7]);
}

// ===================== Kernel A: QKV via fp16 mma (unchanged R9) ===========
#define STRH 72
#define QA_BYTES (64*STRH*2)                   // 9216
#define QB_OFF   QA_BYTES
#define QCHUNK   (QA_BYTES + 192*STRH*2)       // 36864
#define QKV_SMEM (2*QCHUNK)                    // 73728

__global__ __launch_bounds__(256, 2) void qkv_mma_kernel(const float* __restrict__ x)
{
    extern __shared__ __half smh[];
    const uint32_t sbase = smem_u32(smh);
    const int tid    = threadIdx.x;
    const int lane   = tid & 31;
    const int wid    = tid >> 5;
    const int warp_m = wid >> 2;
    const int warp_n = wid & 3;
    const int row0   = blockIdx.x * 64;

    const int lr = lane >> 2;
    const int lc = lane & 3;

    float acc[2][6][4];
    #pragma unroll
    for (int mt = 0; mt < 2; mt++)
        #pragma unroll
        for (int nt = 0; nt < 6; nt++)
            #pragma unroll
            for (int i = 0; i < 4; i++) acc[mt][nt][i] = 0.f;

    const int ar   = tid >> 2;
    const int aseg = tid & 3;

    float4 ra[4];
    auto ldg_a = [&](int c) {
        const float* src = &x[(size_t)(row0 + ar) * CC + c * 64 + aseg * 16];
        #pragma unroll
        for (int l = 0; l < 4; l++) ra[l] = *(const float4*)(src + l * 4);
    };
    auto sts_a = [&](uint32_t bufoff) {
        char* dst = (char*)smh + bufoff + ((uint32_t)(ar * STRH + aseg * 16)) * 2;
        uint4 u0 = make_uint4(pack_h2(ra[0].x, ra[0].y), pack_h2(ra[0].z, ra[0].w),
                              pack_h2(ra[1].x, ra[1].y), pack_h2(ra[1].z, ra[1].w));
        uint4 u1 = make_uint4(pack_h2(ra[2].x, ra[2].y), pack_h2(ra[2].z, ra[2].w),
                              pack_h2(ra[3].x, ra[3].y), pack_h2(ra[3].z, ra[3].w));
        *(uint4*)dst = u0;
        *(uint4*)(dst + 16) = u1;
    };
    auto cp_b = [&](int c, uint32_t bufoff) {
        #pragma unroll
        for (int l = 0; l < 6; l++) {
            int idx = tid + l * 256;
            int n   = idx >> 3;
            int sg  = idx & 7;
            cp_async16(sbase + bufoff + QB_OFF + (uint32_t)(n * STRH + sg * 8) * 2,
                       &g_wth[(size_t)n * 1024 + c * 64 + sg * 8]);
        }
    };

    const uint32_t aoff =
        ((uint32_t)(warp_m * 32 + (lane & 7) + ((lane >> 3) & 1) * 8) * STRH
         + ((lane >> 4) & 1) * 8) * 2;
    const uint32_t boff = QB_OFF +
        ((uint32_t)(warp_n * 48 + (lane & 7) + ((lane >> 4) & 1) * 8) * STRH
         + ((lane >> 3) & 1) * 8) * 2;

    ldg_a(0); sts_a(0);
    cp_b(0, 0);        CP_COMMIT();
    cp_b(1, QCHUNK);   CP_COMMIT();
    ldg_a(1);

    for (int c = 0; c < 16; c++) {
        CP_WAIT1();
        __syncthreads();

        const uint32_t bufoff = (uint32_t)(c & 1) * QCHUNK;
        const uint32_t abase  = sbase + bufoff + aoff;
        const uint32_t bbase  = sbase + bufoff + boff;

        #pragma unroll
        for (int ks = 0; ks < 4; ks++) {
            uint32_t af[2][4];
            #pragma unroll
            for (int mt = 0; mt < 2; mt++)
                ldmatrix_x4(af[mt], abase + mt * (16 * STRH * 2) + ks * 32);
            uint32_t bf[12];
            #pragma unroll
            for (int j = 0; j < 3; j++)
                ldmatrix_x4(&bf[j * 4], bbase + j * (16 * STRH * 2) + ks * 32);
            #pragma unroll
            for (int mt = 0; mt < 2; mt++)
                #pragma unroll
                for (int nt = 0; nt < 6; nt++)
                    mma_f16_16n8k16(acc[mt][nt], af[mt],
                                    &bf[(nt >> 1) * 4 + (nt & 1) * 2]);
        }

        if (c + 1 < 16) {
            sts_a((uint32_t)((c + 1) & 1) * QCHUNK);
            if (c + 2 < 16) ldg_a(c + 2);
        }
        __syncthreads();

        if (c + 2 < 16) cp_b(c + 2, bufoff);
        CP_COMMIT();
    }

    #pragma unroll
    for (int mt = 0; mt < 2; mt++) {
        int rg = row0 + warp_m * 32 + mt * 16 + lr;
        #pragma unroll
        for (int nt = 0; nt < 6; nt++) {
            int ng = warp_n * 48 + nt * 8 + lc * 2;
            int m  = ng >> 6;
            int d  = ng & 63;
            __half* base = (m == 0) ? g_qh : (m == 1) ? g_kh : g_vh;
            *(uint32_t*)&base[(size_t)rg * DD + d] =
                pack_h2(acc[mt][nt][0], acc[mt][nt][1]);
            *(uint32_t*)&base[(size_t)(rg + 8) * DD + d] =
                pack_h2(acc[mt][nt][2], acc[mt][nt][3]);
        }
    }
}

// ===================== Kernel B: attention via fp16 mma ====================
// 2 CTAs/SM; K and V in separate commit groups (V drains behind QK^T).
#define KSTR 72
#define SKB  0
#define SVB  (256*KSTR*2)                  // 36864
#define REDB (2*256*KSTR*2)                // 73728
#define ATT_SMEM (REDB + 1024)             // 74752
#define PSTR32 132
#define SO_STRIDE 66

__global__ __launch_bounds__(256, 2) void attn_kernel(float* __restrict__ out)
{
    extern __shared__ __half smh[];
    const uint32_t sbase = smem_u32(smh);
    float*    sRed = (float*)((char*)smh + REDB);
    uint32_t* sP32 = (uint32_t*)smh;
    float*    sO   = (float*)smh;

    const int tid  = threadIdx.x;
    const int wid  = tid >> 5;
    const int lane = tid & 31;
    const int wm   = wid >> 1;
    const int wn   = wid & 1;
    const int lr   = lane >> 2;
    const int lc   = lane & 3;

    const int qt = blockIdx.x;
    const int bb = blockIdx.y;
    const int q0 = qt * 64;
    const int rows = q0 + 64;              // causal prefix length

    // ---- cp.async stage K (group 0), V (group 1) ----
    const __half* kb = g_kh + (size_t)bb * TT * DD;
    const __half* vb = g_vh + (size_t)bb * TT * DD;
    for (int idx = tid; idx < rows * 8; idx += 256) {
        int s  = idx >> 3;
        int sg = idx & 7;
        cp_async16(sbase + SKB + (uint32_t)(s * KSTR + sg * 8) * 2,
                   &kb[s * DD + sg * 8]);
    }
    CP_COMMIT();
    for (int idx = tid; idx < rows * 8; idx += 256) {
        int s  = idx >> 3;
        int sg = idx & 7;
        cp_async16(sbase + SVB + (uint32_t)(s * KSTR + sg * 8) * 2,
                   &vb[s * DD + sg * 8]);
    }
    CP_COMMIT();

    // ---- Q fragments from gmem ----
    uint32_t qf[4][4];
    {
        const uint32_t* q32 =
            (const uint32_t*)(g_qh + (size_t)(bb * TT + q0 + wm * 16 + lr) * DD);
        const uint32_t* q32b = q32 + 8 * 32;
        #pragma unroll
        for (int ks = 0; ks < 4; ks++) {
            qf[ks][0] = q32 [ks * 8 + lc];
            qf[ks][1] = q32b[ks * 8 + lc];
            qf[ks][2] = q32 [ks * 8 + lc + 4];
            qf[ks][3] = q32b[ks * 8 + lc + 4];
        }
    }
    CP_WAIT1();           // K ready; V still in flight
    __syncthreads();

    const int ntv = min(16, max(0, (q0 + 64 - wn * 128) / 8));
    const int ng2 = ntv >> 1;

    // ---- QK^T ----
    float sacc[16][4];
    #pragma unroll
    for (int nt = 0; nt < 16; nt++)
        #pragma unroll
        for (int i = 0; i < 4; i++) sacc[nt][i] = 0.f;

    {
        const uint32_t kbase = sbase + SKB +
            ((uint32_t)(wn * 128 + (lane & 7) + ((lane >> 4) & 1) * 8) * KSTR
             + ((lane >> 3) & 1) * 8) * 2;
        #pragma unroll
        for (int g = 0; g < 8; g++) {
            if (g >= ng2) break;
            #pragma unroll
            for (int ks = 0; ks < 4; ks++) {
                uint32_t bf[4];
                ldmatrix_x4(bf, kbase + g * (16 * KSTR * 2) + ks * 32);
                mma_f16_16n8k16(sacc[2*g],     qf[ks], &bf[0]);
                mma_f16_16n8k16(sacc[2*g + 1], qf[ks], &bf[2]);
            }
        }
    }

    // ---- scale + causal mask + row max ----
    const int row_g0 = q0 + wm * 16 + lr;
    float mrow[2] = {-INFINITY, -INFINITY};
    #pragma unroll
    for (int nt = 0; nt < 16; nt++) {
        if (nt >= ntv) break;
        #pragma unroll
        for (int i = 0; i < 4; i++) {
            int col = wn * 128 + nt * 8 + 2 * lc + (i & 1);
            int row = row_g0 + ((i >> 1) << 3);
            float v = sacc[nt][i] * 0.03125f;
            v = (col <= row) ? v : -INFINITY;
            sacc[nt][i] = v;
            if (i < 2) mrow[0] = fmaxf(mrow[0], v);
            else       mrow[1] = fmaxf(mrow[1], v);
        }
    }
    #pragma unroll
    for (int off = 1; off <= 2; off <<= 1) {
        mrow[0] = fmaxf(mrow[0], __shfl_xor_sync(0xFFFFFFFF, mrow[0], off));
        mrow[1] = fmaxf(mrow[1], __shfl_xor_sync(0xFFFFFFFF, mrow[1], off));
    }
    if (lc == 0) {
        sRed[wn * 64 + wm * 16 + lr]     = mrow[0];
        sRed[wn * 64 + wm * 16 + lr + 8] = mrow[1];
    }
    CP_WAIT0();           // V ready (overlapped with QK^T + masking)
    __syncthreads();      // K region now reusable as P; V visible to all

    float gm0 = fmaxf(sRed[wm * 16 + lr],     sRed[64 + wm * 16 + lr]);
    float gm1 = fmaxf(sRed[wm * 16 + lr + 8], sRed[64 + wm * 16 + lr + 8]);

    // ---- exp, store P (half2), partial sums ----
    float srow[2] = {0.f, 0.f};
    #pragma unroll
    for (int nt = 0; nt < 16; nt++) {
        if (nt >= ntv) break;
        float e0 = __expf(sacc[nt][0] - gm0);
        float e1 = __expf(sacc[nt][1] - gm0);
        float e2 = __expf(sacc[nt][2] - gm1);
        float e3 = __expf(sacc[nt][3] - gm1);
        srow[0] += e0 + e1;
        srow[1] += e2 + e3;
        uint32_t* p0 = sP32 + (wm * 16 + lr) * PSTR32 + wn * 64 + nt * 4 + lc;
        p0[0]            = pack_h2(e0, e1);
        p0[8 * PSTR32]   = pack_h2(e2, e3);
    }
    #pragma unroll
    for (int off = 1; off <= 2; off <<= 1) {
        srow[0] += __shfl_xor_sync(0xFFFFFFFF, srow[0], off);
        srow[1] += __shfl_xor_sync(0xFFFFFFFF, srow[1], off);
    }
    if (lc == 0) {
        sRed[128 + wn * 64 + wm * 16 + lr]     = srow[0];
        sRed[128 + wn * 64 + wm * 16 + lr + 8] = srow[1];
    }
    __syncthreads();

    const float inv0 = 1.f / (sRed[128 + wm * 16 + lr] +
                              sRed[128 + 64 + wm * 16 + lr]);
    const float inv1 = 1.f / (sRed[128 + wm * 16 + lr + 8] +
                              sRed[128 + 64 + wm * 16 + lr + 8]);

    // ---- PV ----
    float oacc[8][4];
    #pragma unroll
    for (int nt = 0; nt < 8; nt++)
        #pragma unroll
        for (int i = 0; i < 4; i++) oacc[nt][i] = 0.f;

    {
        const uint32_t vbase = sbase + SVB +
            ((uint32_t)(wn * 128 + (lane & 7) + ((lane >> 3) & 1) * 8) * KSTR
             + ((lane >> 4) & 1) * 8) * 2;
        for (int ks2 = 0; ks2 < ng2; ks2++) {
            uint32_t af[4];
            const uint32_t* ap = sP32 + (wm * 16 + lr) * PSTR32 + wn * 64 + ks2 * 8;
            af[0] = ap[lc];
            af[1] = ap[8 * PSTR32 + lc];
            af[2] = ap[lc + 4];
            af[3] = ap[8 * PSTR32 + lc + 4];
            #pragma unroll
            for (int pr = 0; pr < 4; pr++) {
                uint32_t bf[4];
                ldmatrix_x4_trans(bf, vbase + ks2 * (16 * KSTR * 2) + pr * 32);
                mma_f16_16n8k16(oacc[2*pr],     af, &bf[0]);
                mma_f16_16n8k16(oacc[2*pr + 1], af, &bf[2]);
            }
        }
    }
    __syncthreads();

    // ---- cross-warp_n reduction + output ----
    if (wn == 0) {
        #pragma unroll
        for (int nt = 0; nt < 8; nt++) {
            float* o0 = sO + (wm * 16 + lr) * SO_STRIDE + nt * 8 + 2 * lc;
            *(float2*)o0 = make_float2(oacc[nt][0], oacc[nt][1]);
            float* o1 = o0 + 8 * SO_STRIDE;
            *(float2*)o1 = make_float2(oacc[nt][2], oacc[nt][3]);
        }
    }
    __syncthreads();
    if (wn == 1) {
        const size_t orow = (size_t)(bb * TT + q0 + wm * 16 + lr) * DD;
        #pragma unroll
        for (int nt = 0; nt < 8; nt++) {
            const float* o0 = sO + (wm * 16 + lr) * SO_STRIDE + nt * 8 + 2 * lc;
            const float* o1 = o0 + 8 * SO_STRIDE;
            float2 r0 = make_float2((oacc[nt][0] + o0[0]) * inv0,
                                    (oacc[nt][1] + o0[1]) * inv0);
            float2 r1 = make_float2((oacc[nt][2] + o1[0]) * inv1,
                                    (oacc[nt][3] + o1[1]) * inv1);
            *(float2*)&out[orow + nt * 8 + 2 * lc] = r0;
            *(float2*)&out[orow + 8 * DD + nt * 8 + 2 * lc] = r1;
        }
    }
}

// ---------------------------------------------------------------------------
extern "C" void kernel_launch(void* const* d_in, const int* in_sizes, int n_in,
                              void* d_out, int out_size)
{
    (void)in_sizes; (void)n_in; (void)out_size;
    const float* x  = (const float*)d_in[0];
    const float* Wq = (const float*)d_in[1];
    const float* Wk = (const float*)d_in[2];
    const float* Wv = (const float*)d_in[3];
    float* out = (float*)d_out;

    cudaFuncSetAttribute(qkv_mma_kernel,
                         cudaFuncAttributeMaxDynamicSharedMemorySize, QKV_SMEM);
    cudaFuncSetAttribute(attn_kernel,
                         cudaFuncAttributeMaxDynamicSharedMemorySize, ATT_SMEM);

    transpose_w_kernel<<<48, 256>>>(Wq, Wk, Wv);
    qkv_mma_kernel<<<BT / 64, 256, QKV_SMEM>>>(x);
    attn_kernel<<<dim3(4, BB), 256, ATT_SMEM>>>(out);
}

// round 11
// speedup vs baseline: 1.9967x; 1.0280x over previous
#include <cuda_runtime.h>
#include <cuda_fp16.h>
#include <math.h>
#include <cstdint>

#define BB 256
#define TT 256
#define CC 1024
#define DD 64
#define BT (BB*TT)

// Scratch: Q, K, V as half (8 MB each) + transposed W as half (384 KB)
__device__ __half g_qh[BT*DD];
__device__ __half g_kh[BT*DD];
__device__ __half g_vh[BT*DD];
__device__ __half g_wth[192*1024];   // K-major: rows 0-63 Wq^T, 64-127 Wk^T, 128-191 Wv^T

// ===================== PTX helpers (sm_80+ PTX, ok on compute_103) =========
__device__ __forceinline__ void mma_f16_16n8k16(
    float d[4], const uint32_t a[4], const uint32_t b[2])
{
    asm volatile(
        "mma.sync.aligned.m16n8k16.row.col.f32.f16.f16.f32 "
        "{%0,%1,%2,%3}, {%4,%5,%6,%7}, {%8,%9}, {%0,%1,%2,%3};"
        : "+f"(d[0]), "+f"(d[1]), "+f"(d[2]), "+f"(d[3])
        : "r"(a[0]), "r"(a[1]), "r"(a[2]), "r"(a[3]),
          "r"(b[0]), "r"(b[1]));
}

__device__ __forceinline__ void ldmatrix_x4(uint32_t r[4], uint32_t addr) {
    asm volatile("ldmatrix.sync.aligned.m8n8.x4.shared.b16 {%0,%1,%2,%3}, [%4];"
        : "=r"(r[0]), "=r"(r[1]), "=r"(r[2]), "=r"(r[3]) : "r"(addr));
}

__device__ __forceinline__ void ldmatrix_x4_trans(uint32_t r[4], uint32_t addr) {
    asm volatile("ldmatrix.sync.aligned.m8n8.x4.trans.shared.b16 {%0,%1,%2,%3}, [%4];"
        : "=r"(r[0]), "=r"(r[1]), "=r"(r[2]), "=r"(r[3]) : "r"(addr));
}

__device__ __forceinline__ void cp_async16(uint32_t dst, const void* src) {
    asm volatile("cp.async.cg.shared.global [%0], [%1], 16;"
        :: "r"(dst), "l"(src) : "memory");
}
#define CP_COMMIT() asm volatile("cp.async.commit_group;" ::: "memory")
#define CP_WAIT1()  asm volatile("cp.async.wait_group 1;" ::: "memory")
#define CP_WAIT0()  asm volatile("cp.async.wait_group 0;" ::: "memory")

__device__ __forceinline__ uint32_t smem_u32(const void* p) {
    uint32_t a;
    asm("{ .reg .u64 t; cvta.to.shared.u64 t, %1; cvt.u32.u64 %0, t; }"
        : "=r"(a) : "l"(p));
    return a;
}

__device__ __forceinline__ uint32_t pack_h2(float a, float b) {
    half2 h = __floats2half2_rn(a, b);
    return *(uint32_t*)&h;
}

// ===================== Kernel 0: coalesced tile-transpose of W =============
__global__ __launch_bounds__(256) void transpose_w_kernel(
    const float* __restrict__ Wq, const float* __restrict__ Wk,
    const float* __restrict__ Wv)
{
    __shared__ float tile[64][65];
    const int m  = blockIdx.x >> 4;          // 0..2
    const int kt = blockIdx.x & 15;          // 0..15
    const float* W = (m == 0) ? Wq : (m == 1) ? Wk : Wv;

    const int r   = threadIdx.x >> 2;        // 0..63
    const int seg = threadIdx.x & 3;         // 0..3 (16 floats each)
    #pragma unroll
    for (int l = 0; l < 4; l++) {
        float4 v = *(const float4*)&W[(size_t)(kt * 64 + r) * 64 + seg * 16 + l * 4];
        tile[r][seg * 16 + l * 4 + 0] = v.x;
        tile[r][seg * 16 + l * 4 + 1] = v.y;
        tile[r][seg * 16 + l * 4 + 2] = v.z;
        tile[r][seg * 16 + l * 4 + 3] = v.w;
    }
    __syncthreads();

    const int n = r;
    uint32_t u[8];
    #pragma unroll
    for (int i = 0; i < 8; i++)
        u[i] = pack_h2(tile[seg * 16 + 2 * i][n], tile[seg * 16 + 2 * i + 1][n]);
    char* dst = (char*)&g_wth[(size_t)(m * 64 + n) * 1024 + kt * 64 + seg * 16];
    *(uint4*)dst        = make_uint4(u[0], u[1], u[2], u[3]);
    *(uint4*)(dst + 16) = make_uint4(u[4], u[5], u[6], u[7]);
}

// ===================== Kernel A: QKV via fp16 mma (unchanged R9) ===========
#define STRH 72
#define QA_BYTES (64*STRH*2)                   // 9216
#define QB_OFF   QA_BYTES
#define QCHUNK   (QA_BYTES + 192*STRH*2)       // 36864
#define QKV_SMEM (2*QCHUNK)                    // 73728

__global__ __launch_bounds__(256, 2) void qkv_mma_kernel(const float* __restrict__ x)
{
    extern __shared__ __half smh[];
    const uint32_t sbase = smem_u32(smh);
    const int tid    = threadIdx.x;
    const int lane   = tid & 31;
    const int wid    = tid >> 5;
    const int warp_m = wid >> 2;
    const int warp_n = wid & 3;
    const int row0   = blockIdx.x * 64;

    const int lr = lane >> 2;
    const int lc = lane & 3;

    float acc[2][6][4];
    #pragma unroll
    for (int mt = 0; mt < 2; mt++)
        #pragma unroll
        for (int nt = 0; nt < 6; nt++)
            #pragma unroll
            for (int i = 0; i < 4; i++) acc[mt][nt][i] = 0.f;

    const int ar   = tid >> 2;
    const int aseg = tid & 3;

    float4 ra[4];
    auto ldg_a = [&](int c) {
        const float* src = &x[(size_t)(row0 + ar) * CC + c * 64 + aseg * 16];
        #pragma unroll
        for (int l = 0; l < 4; l++) ra[l] = *(const float4*)(src + l * 4);
    };
    auto sts_a = [&](uint32_t bufoff) {
        char* dst = (char*)smh + bufoff + ((uint32_t)(ar * STRH + aseg * 16)) * 2;
        uint4 u0 = make_uint4(pack_h2(ra[0].x, ra[0].y), pack_h2(ra[0].z, ra[0].w),
                              pack_h2(ra[1].x, ra[1].y), pack_h2(ra[1].z, ra[1].w));
        uint4 u1 = make_uint4(pack_h2(ra[2].x, ra[2].y), pack_h2(ra[2].z, ra[2].w),
                              pack_h2(ra[3].x, ra[3].y), pack_h2(ra[3].z, ra[3].w));
        *(uint4*)dst = u0;
        *(uint4*)(dst + 16) = u1;
    };
    auto cp_b = [&](int c, uint32_t bufoff) {
        #pragma unroll
        for (int l = 0; l < 6; l++) {
            int idx = tid + l * 256;
            int n   = idx >> 3;
            int sg  = idx & 7;
            cp_async16(sbase + bufoff + QB_OFF + (uint32_t)(n * STRH + sg * 8) * 2,
                       &g_wth[(size_t)n * 1024 + c * 64 + sg * 8]);
        }
    };

    const uint32_t aoff =
        ((uint32_t)(warp_m * 32 + (lane & 7) + ((lane >> 3) & 1) * 8) * STRH
         + ((lane >> 4) & 1) * 8) * 2;
    const uint32_t boff = QB_OFF +
        ((uint32_t)(warp_n * 48 + (lane & 7) + ((lane >> 4) & 1) * 8) * STRH
         + ((lane >> 3) & 1) * 8) * 2;

    ldg_a(0); sts_a(0);
    cp_b(0, 0);        CP_COMMIT();
    cp_b(1, QCHUNK);   CP_COMMIT();
    ldg_a(1);

    for (int c = 0; c < 16; c++) {
        CP_WAIT1();
        __syncthreads();

        const uint32_t bufoff = (uint32_t)(c & 1) * QCHUNK;
        const uint32_t abase  = sbase + bufoff + aoff;
        const uint32_t bbase  = sbase + bufoff + boff;

        #pragma unroll
        for (int ks = 0; ks < 4; ks++) {
            uint32_t af[2][4];
            #pragma unroll
            for (int mt = 0; mt < 2; mt++)
                ldmatrix_x4(af[mt], abase + mt * (16 * STRH * 2) + ks * 32);
            uint32_t bf[12];
            #pragma unroll
            for (int j = 0; j < 3; j++)
                ldmatrix_x4(&bf[j * 4], bbase + j * (16 * STRH * 2) + ks * 32);
            #pragma unroll
            for (int mt = 0; mt < 2; mt++)
                #pragma unroll
                for (int nt = 0; nt < 6; nt++)
                    mma_f16_16n8k16(acc[mt][nt], af[mt],
                                    &bf[(nt >> 1) * 4 + (nt & 1) * 2]);
        }

        if (c + 1 < 16) {
            sts_a((uint32_t)((c + 1) & 1) * QCHUNK);
            if (c + 2 < 16) ldg_a(c + 2);
        }
        __syncthreads();

        if (c + 2 < 16) cp_b(c + 2, bufoff);
        CP_COMMIT();
    }

    #pragma unroll
    for (int mt = 0; mt < 2; mt++) {
        int rg = row0 + warp_m * 32 + mt * 16 + lr;
        #pragma unroll
        for (int nt = 0; nt < 6; nt++) {
            int ng = warp_n * 48 + nt * 8 + lc * 2;
            int m  = ng >> 6;
            int d  = ng & 63;
            __half* base = (m == 0) ? g_qh : (m == 1) ? g_kh : g_vh;
            *(uint32_t*)&base[(size_t)rg * DD + d] =
                pack_h2(acc[mt][nt][0], acc[mt][nt][1]);
            *(uint32_t*)&base[(size_t)(rg + 8) * DD + d] =
                pack_h2(acc[mt][nt][2], acc[mt][nt][3]);
        }
    }
}

// ===================== Kernel B: attention, register pass-through ==========
// No max pass (shift m=0 is safe: |score| << 11); exp applied in-register on
// QK^T D-fragments which ARE the PV A-fragments (FA2 layout identity).
// 3 syncs total. smem: K (reused as O-exchange) + V + 128-float sum array.
#define KSTR 72
#define SKB  0
#define SVB  (256*KSTR*2)                  // 36864
#define REDB (2*256*KSTR*2)                // 73728
#define ATT_SMEM (REDB + 512)              // 74240
#define SO_STRIDE 66

__global__ __launch_bounds__(256, 2) void attn_kernel(float* __restrict__ out)
{
    extern __shared__ __half smh[];
    const uint32_t sbase = smem_u32(smh);
    float* sRed = (float*)((char*)smh + REDB);   // 128 floats: row sums
    float* sO   = (float*)smh;                   // overlays K after QK^T

    const int tid  = threadIdx.x;
    const int wid  = tid >> 5;
    const int lane = tid & 31;
    const int wm   = wid >> 1;          // 0..3: 16 q-rows each
    const int wn   = wid & 1;           // 0..1: 128 keys each
    const int lr   = lane >> 2;
    const int lc   = lane & 3;

    const int qt = blockIdx.x;
    const int bb = blockIdx.y;
    const int q0 = qt * 64;
    const int rows = q0 + 64;           // causal prefix length

    // ---- cp.async stage K (group 0), V (group 1) ----
    const __half* kb = g_kh + (size_t)bb * TT * DD;
    const __half* vb = g_vh + (size_t)bb * TT * DD;
    for (int idx = tid; idx < rows * 8; idx += 256) {
        int s  = idx >> 3;
        int sg = idx & 7;
        cp_async16(sbase + SKB + (uint32_t)(s * KSTR + sg * 8) * 2,
                   &kb[s * DD + sg * 8]);
    }
    CP_COMMIT();
    for (int idx = tid; idx < rows * 8; idx += 256) {
        int s  = idx >> 3;
        int sg = idx & 7;
        cp_async16(sbase + SVB + (uint32_t)(s * KSTR + sg * 8) * 2,
                   &vb[s * DD + sg * 8]);
    }
    CP_COMMIT();

    // ---- Q fragments from gmem ----
    uint32_t qf[4][4];
    {
        const uint32_t* q32 =
            (const uint32_t*)(g_qh + (size_t)(bb * TT + q0 + wm * 16 + lr) * DD);
        const uint32_t* q32b = q32 + 8 * 32;
        #pragma unroll
        for (int ks = 0; ks < 4; ks++) {
            qf[ks][0] = q32 [ks * 8 + lc];
            qf[ks][1] = q32b[ks * 8 + lc];
            qf[ks][2] = q32 [ks * 8 + lc + 4];
            qf[ks][3] = q32b[ks * 8 + lc + 4];
        }
    }
    CP_WAIT1();            // K ready; V still in flight
    __syncthreads();       // sync 1

    const int ntv = min(16, max(0, (q0 + 64 - wn * 128) / 8));
    const int ng2 = ntv >> 1;           // 16-key groups

    const int r0 = q0 + wm * 16 + lr;   // global q row (low)
    const int r1 = r0 + 8;
    const float SC = 0.03125f;          // C^-0.5

    // ---- QK^T + exp fused; P stays in registers (pf) ----
    uint32_t pf[8][4];
    float srow[2] = {0.f, 0.f};
    {
        const uint32_t kbase = sbase + SKB +
            ((uint32_t)(wn * 128 + (lane & 7) + ((lane >> 4) & 1) * 8) * KSTR
             + ((lane >> 3) & 1) * 8) * 2;
        #pragma unroll
        for (int g = 0; g < 8; g++) {
            if (g >= ng2) break;
            float s0[4] = {0.f, 0.f, 0.f, 0.f};
            float s1[4] = {0.f, 0.f, 0.f, 0.f};
            #pragma unroll
            for (int ks = 0; ks < 4; ks++) {
                uint32_t bf[4];
                ldmatrix_x4(bf, kbase + g * (16 * KSTR * 2) + ks * 32);
                mma_f16_16n8k16(s0, qf[ks], &bf[0]);
                mma_f16_16n8k16(s1, qf[ks], &bf[2]);
            }
            const int cb = wn * 128 + g * 16 + 2 * lc;
            float e00 = (cb     <= r0) ? __expf(s0[0] * SC) : 0.f;
            float e01 = (cb + 1 <= r0) ? __expf(s0[1] * SC) : 0.f;
            float e02 = (cb     <= r1) ? __expf(s0[2] * SC) : 0.f;
            float e03 = (cb + 1 <= r1) ? __expf(s0[3] * SC) : 0.f;
            float e10 = (cb + 8 <= r0) ? __expf(s1[0] * SC) : 0.f;
            float e11 = (cb + 9 <= r0) ? __expf(s1[1] * SC) : 0.f;
            float e12 = (cb + 8 <= r1) ? __expf(s1[2] * SC) : 0.f;
            float e13 = (cb + 9 <= r1) ? __expf(s1[3] * SC) : 0.f;
            srow[0] += e00 + e01 + e10 + e11;
            srow[1] += e02 + e03 + e12 + e13;
            pf[g][0] = pack_h2(e00, e01);   // row lr,  k 0..7  of group
            pf[g][1] = pack_h2(e02, e03);   // row lr+8, k 0..7
            pf[g][2] = pack_h2(e10, e11);   // row lr,  k 8..15
            pf[g][3] = pack_h2(e12, e13);   // row lr+8, k 8..15
        }
    }

    // row-sum exchange (quad shuffle then smem)
    #pragma unroll
    for (int off = 1; off <= 2; off <<= 1) {
        srow[0] += __shfl_xor_sync(0xFFFFFFFF, srow[0], off);
        srow[1] += __shfl_xor_sync(0xFFFFFFFF, srow[1], off);
    }
    if (lc == 0) {
        sRed[wn * 64 + wm * 16 + lr]     = srow[0];
        sRed[wn * 64 + wm * 16 + lr + 8] = srow[1];
    }

    CP_WAIT0();            // V ready (drained behind QK^T)
    __syncthreads();       // sync 2: V + sums visible; K region now dead

    const float inv0 = 1.f / (sRed[wm * 16 + lr]     + sRed[64 + wm * 16 + lr]);
    const float inv1 = 1.f / (sRed[wm * 16 + lr + 8] + sRed[64 + wm * 16 + lr + 8]);

    // ---- PV: A-fragments straight from pf registers ----
    float oacc[8][4];
    #pragma unroll
    for (int nt = 0; nt < 8; nt++)
        #pragma unroll
        for (int i = 0; i < 4; i++) oacc[nt][i] = 0.f;

    {
        const uint32_t vbase = sbase + SVB +
            ((uint32_t)(wn * 128 + (lane & 7) + ((lane >> 3) & 1) * 8) * KSTR
             + ((lane >> 4) & 1) * 8) * 2;
        #pragma unroll
        for (int g = 0; g < 8; g++) {
            if (g >= ng2) break;
            #pragma unroll
            for (int pr = 0; pr < 4; pr++) {
                uint32_t bf[4];
                ldmatrix_x4_trans(bf, vbase + g * (16 * KSTR * 2) + pr * 32);
                mma_f16_16n8k16(oacc[2*pr],     pf[g], &bf[0]);
                mma_f16_16n8k16(oacc[2*pr + 1], pf[g], &bf[2]);
            }
        }
    }

    // ---- cross-warp_n reduction (sO overlays dead K region) + output ----
    if (wn == 0) {
        #pragma unroll
        for (int nt = 0; nt < 8; nt++) {
            float* o0 = sO + (wm * 16 + lr) * SO_STRIDE + nt * 8 + 2 * lc;
            *(float2*)o0 = make_float2(oacc[nt][0], oacc[nt][1]);
            float* o1 = o0 + 8 * SO_STRIDE;
            *(float2*)o1 = make_float2(oacc[nt][2], oacc[nt][3]);
        }
    }
    __syncthreads();       // sync 3
    if (wn == 1) {
        const size_t orow = (size_t)(bb * TT + q0 + wm * 16 + lr) * DD;
        #pragma unroll
        for (int nt = 0; nt < 8; nt++) {
            const float* o0 = sO + (wm * 16 + lr) * SO_STRIDE + nt * 8 + 2 * lc;
            const float* o1 = o0 + 8 * SO_STRIDE;
            float2 r0v = make_float2((oacc[nt][0] + o0[0]) * inv0,
                                     (oacc[nt][1] + o0[1]) * inv0);
            float2 r1v = make_float2((oacc[nt][2] + o1[0]) * inv1,
                                     (oacc[nt][3] + o1[1]) * inv1);
            *(float2*)&out[orow + nt * 8 + 2 * lc] = r0v;
            *(float2*)&out[orow + 8 * DD + nt * 8 + 2 * lc] = r1v;
        }
    }
}

// ---------------------------------------------------------------------------
extern "C" void kernel_launch(void* const* d_in, const int* in_sizes, int n_in,
                              void* d_out, int out_size)
{
    (void)in_sizes; (void)n_in; (void)out_size;
    const float* x  = (const float*)d_in[0];
    const float* Wq = (const float*)d_in[1];
    const float* Wk = (const float*)d_in[2];
    const float* Wv = (const float*)d_in[3];
    float* out = (float*)d_out;

    cudaFuncSetAttribute(qkv_mma_kernel,
                         cudaFuncAttributeMaxDynamicSharedMemorySize, QKV_SMEM);
    cudaFuncSetAttribute(attn_kernel,
                         cudaFuncAttributeMaxDynamicSharedMemorySize, ATT_SMEM);

    transpose_w_kernel<<<48, 256>>>(Wq, Wk, Wv);
    qkv_mma_kernel<<<BT / 64, 256, QKV_SMEM>>>(x);
    attn_kernel<<<dim3(4, BB), 256, ATT_SMEM>>>(out);
}

// round 12
// speedup vs baseline: 2.0010x; 1.0022x over previous
#include <cuda_runtime.h>
#include <cuda_fp16.h>
#include <math.h>
#include <cstdint>

#define BB 256
#define TT 256
#define CC 1024
#define DD 64
#define BT (BB*TT)

// Scratch: Q, K, V as half (8 MB each) + transposed W as half (384 KB)
__device__ __half g_qh[BT*DD];
__device__ __half g_kh[BT*DD];
__device__ __half g_vh[BT*DD];
__device__ __half g_wth[192*1024];   // K-major: rows 0-63 Wq^T, 64-127 Wk^T, 128-191 Wv^T

// ===================== PTX helpers (sm_80+ PTX, ok on compute_103) =========
__device__ __forceinline__ void mma_f16_16n8k16(
    float d[4], const uint32_t a[4], const uint32_t b[2])
{
    asm volatile(
        "mma.sync.aligned.m16n8k16.row.col.f32.f16.f16.f32 "
        "{%0,%1,%2,%3}, {%4,%5,%6,%7}, {%8,%9}, {%0,%1,%2,%3};"
        : "+f"(d[0]), "+f"(d[1]), "+f"(d[2]), "+f"(d[3])
        : "r"(a[0]), "r"(a[1]), "r"(a[2]), "r"(a[3]),
          "r"(b[0]), "r"(b[1]));
}

__device__ __forceinline__ void ldmatrix_x4(uint32_t r[4], uint32_t addr) {
    asm volatile("ldmatrix.sync.aligned.m8n8.x4.shared.b16 {%0,%1,%2,%3}, [%4];"
        : "=r"(r[0]), "=r"(r[1]), "=r"(r[2]), "=r"(r[3]) : "r"(addr));
}

__device__ __forceinline__ void ldmatrix_x4_trans(uint32_t r[4], uint32_t addr) {
    asm volatile("ldmatrix.sync.aligned.m8n8.x4.trans.shared.b16 {%0,%1,%2,%3}, [%4];"
        : "=r"(r[0]), "=r"(r[1]), "=r"(r[2]), "=r"(r[3]) : "r"(addr));
}

__device__ __forceinline__ void cp_async16(uint32_t dst, const void* src) {
    asm volatile("cp.async.cg.shared.global [%0], [%1], 16;"
        :: "r"(dst), "l"(src) : "memory");
}
#define CP_COMMIT() asm volatile("cp.async.commit_group;" ::: "memory")
#define CP_WAIT1()  asm volatile("cp.async.wait_group 1;" ::: "memory")
#define CP_WAIT0()  asm volatile("cp.async.wait_group 0;" ::: "memory")

__device__ __forceinline__ uint32_t smem_u32(const void* p) {
    uint32_t a;
    asm("{ .reg .u64 t; cvta.to.shared.u64 t, %1; cvt.u32.u64 %0, t; }"
        : "=r"(a) : "l"(p));
    return a;
}

__device__ __forceinline__ uint32_t pack_h2(float a, float b) {
    half2 h = __floats2half2_rn(a, b);
    return *(uint32_t*)&h;
}

// ===================== Kernel 0: coalesced tile-transpose of W =============
__global__ __launch_bounds__(256) void transpose_w_kernel(
    const float* __restrict__ Wq, const float* __restrict__ Wk,
    const float* __restrict__ Wv)
{
    __shared__ float tile[64][65];
    const int m  = blockIdx.x >> 4;          // 0..2
    const int kt = blockIdx.x & 15;          // 0..15
    const float* W = (m == 0) ? Wq : (m == 1) ? Wk : Wv;

    const int r   = threadIdx.x >> 2;        // 0..63
    const int seg = threadIdx.x & 3;         // 0..3 (16 floats each)
    #pragma unroll
    for (int l = 0; l < 4; l++) {
        float4 v = *(const float4*)&W[(size_t)(kt * 64 + r) * 64 + seg * 16 + l * 4];
        tile[r][seg * 16 + l * 4 + 0] = v.x;
        tile[r][seg * 16 + l * 4 + 1] = v.y;
        tile[r][seg * 16 + l * 4 + 2] = v.z;
        tile[r][seg * 16 + l * 4 + 3] = v.w;
    }
    __syncthreads();

    const int n = r;
    uint32_t u[8];
    #pragma unroll
    for (int i = 0; i < 8; i++)
        u[i] = pack_h2(tile[seg * 16 + 2 * i][n], tile[seg * 16 + 2 * i + 1][n]);
    char* dst = (char*)&g_wth[(size_t)(m * 64 + n) * 1024 + kt * 64 + seg * 16];
    *(uint4*)dst        = make_uint4(u[0], u[1], u[2], u[3]);
    *(uint4*)(dst + 16) = make_uint4(u[4], u[5], u[6], u[7]);
}

// ===================== Kernel A: QKV via fp16 mma (unchanged R9) ===========
#define STRH 72
#define QA_BYTES (64*STRH*2)                   // 9216
#define QB_OFF   QA_BYTES
#define QCHUNK   (QA_BYTES + 192*STRH*2)       // 36864
#define QKV_SMEM (2*QCHUNK)                    // 73728

__global__ __launch_bounds__(256, 2) void qkv_mma_kernel(const float* __restrict__ x)
{
    extern __shared__ __half smh[];
    const uint32_t sbase = smem_u32(smh);
    const int tid    = threadIdx.x;
    const int lane   = tid & 31;
    const int wid    = tid >> 5;
    const int warp_m = wid >> 2;
    const int warp_n = wid & 3;
    const int row0   = blockIdx.x * 64;

    const int lr = lane >> 2;
    const int lc = lane & 3;

    float acc[2][6][4];
    #pragma unroll
    for (int mt = 0; mt < 2; mt++)
        #pragma unroll
        for (int nt = 0; nt < 6; nt++)
            #pragma unroll
            for (int i = 0; i < 4; i++) acc[mt][nt][i] = 0.f;

    const int ar   = tid >> 2;
    const int aseg = tid & 3;

    float4 ra[4];
    auto ldg_a = [&](int c) {
        const float* src = &x[(size_t)(row0 + ar) * CC + c * 64 + aseg * 16];
        #pragma unroll
        for (int l = 0; l < 4; l++) ra[l] = *(const float4*)(src + l * 4);
    };
    auto sts_a = [&](uint32_t bufoff) {
        char* dst = (char*)smh + bufoff + ((uint32_t)(ar * STRH + aseg * 16)) * 2;
        uint4 u0 = make_uint4(pack_h2(ra[0].x, ra[0].y), pack_h2(ra[0].z, ra[0].w),
                              pack_h2(ra[1].x, ra[1].y), pack_h2(ra[1].z, ra[1].w));
        uint4 u1 = make_uint4(pack_h2(ra[2].x, ra[2].y), pack_h2(ra[2].z, ra[2].w),
                              pack_h2(ra[3].x, ra[3].y), pack_h2(ra[3].z, ra[3].w));
        *(uint4*)dst = u0;
        *(uint4*)(dst + 16) = u1;
    };
    auto cp_b = [&](int c, uint32_t bufoff) {
        #pragma unroll
        for (int l = 0; l < 6; l++) {
            int idx = tid + l * 256;
            int n   = idx >> 3;
            int sg  = idx & 7;
            cp_async16(sbase + bufoff + QB_OFF + (uint32_t)(n * STRH + sg * 8) * 2,
                       &g_wth[(size_t)n * 1024 + c * 64 + sg * 8]);
        }
    };

    const uint32_t aoff =
        ((uint32_t)(warp_m * 32 + (lane & 7) + ((lane >> 3) & 1) * 8) * STRH
         + ((lane >> 4) & 1) * 8) * 2;
    const uint32_t boff = QB_OFF +
        ((uint32_t)(warp_n * 48 + (lane & 7) + ((lane >> 4) & 1) * 8) * STRH
         + ((lane >> 3) & 1) * 8) * 2;

    ldg_a(0); sts_a(0);
    cp_b(0, 0);        CP_COMMIT();
    cp_b(1, QCHUNK);   CP_COMMIT();
    ldg_a(1);

    for (int c = 0; c < 16; c++) {
        CP_WAIT1();
        __syncthreads();

        const uint32_t bufoff = (uint32_t)(c & 1) * QCHUNK;
        const uint32_t abase  = sbase + bufoff + aoff;
        const uint32_t bbase  = sbase + bufoff + boff;

        #pragma unroll
        for (int ks = 0; ks < 4; ks++) {
            uint32_t af[2][4];
            #pragma unroll
            for (int mt = 0; mt < 2; mt++)
                ldmatrix_x4(af[mt], abase + mt * (16 * STRH * 2) + ks * 32);
            uint32_t bf[12];
            #pragma unroll
            for (int j = 0; j < 3; j++)
                ldmatrix_x4(&bf[j * 4], bbase + j * (16 * STRH * 2) + ks * 32);
            #pragma unroll
            for (int mt = 0; mt < 2; mt++)
                #pragma unroll
                for (int nt = 0; nt < 6; nt++)
                    mma_f16_16n8k16(acc[mt][nt], af[mt],
                                    &bf[(nt >> 1) * 4 + (nt & 1) * 2]);
        }

        if (c + 1 < 16) {
            sts_a((uint32_t)((c + 1) & 1) * QCHUNK);
            if (c + 2 < 16) ldg_a(c + 2);
        }
        __syncthreads();

        if (c + 2 < 16) cp_b(c + 2, bufoff);
        CP_COMMIT();
    }

    #pragma unroll
    for (int mt = 0; mt < 2; mt++) {
        int rg = row0 + warp_m * 32 + mt * 16 + lr;
        #pragma unroll
        for (int nt = 0; nt < 6; nt++) {
            int ng = warp_n * 48 + nt * 8 + lc * 2;
            int m  = ng >> 6;
            int d  = ng & 63;
            __half* base = (m == 0) ? g_qh : (m == 1) ? g_kh : g_vh;
            *(uint32_t*)&base[(size_t)rg * DD + d] =
                pack_h2(acc[mt][nt][0], acc[mt][nt][1]);
            *(uint32_t*)&base[(size_t)(rg + 8) * DD + d] =
                pack_h2(acc[mt][nt][2], acc[mt][nt][3]);
        }
    }
}

// ===================== Kernel B: attention, one CTA per batch ==============
// Grid 256. K/V (full 256 rows) staged ONCE; loop over 4 q-tiles in-CTA.
// Register pass-through softmax (no max pass) as in R11.
// smem: K 36864 + V 36864 + O-exchange 16896 + sums 512 = 91136 -> 2 CTAs/SM.
#define KSTR 72
#define SKB  0
#define SVB  (256*KSTR*2)                  // 36864
#define SOB  (2*256*KSTR*2)                // 73728
#define SUMB (SOB + 64*66*4)               // 90624
#define ATT_SMEM (SUMB + 512)              // 91136
#define SO_STRIDE 66

__global__ __launch_bounds__(256, 2) void attn_kernel(float* __restrict__ out)
{
    extern __shared__ __half smh[];
    const uint32_t sbase = smem_u32(smh);
    float* sO   = (float*)((char*)smh + SOB);
    float* sRed = (float*)((char*)smh + SUMB);   // 128 floats: row sums

    const int tid  = threadIdx.x;
    const int wid  = tid >> 5;
    const int lane = tid & 31;
    const int wm   = wid >> 1;          // 0..3: 16 q-rows each
    const int wn   = wid & 1;           // 0..1: 128 keys each
    const int lr   = lane >> 2;
    const int lc   = lane & 3;

    const int bb = blockIdx.x;          // batch

    // ---- stage full K, V once ----
    const __half* kb = g_kh + (size_t)bb * TT * DD;
    const __half* vb = g_vh + (size_t)bb * TT * DD;
    #pragma unroll
    for (int l = 0; l < 8; l++) {
        int idx = tid + l * 256;        // 0..2047
        int s   = idx >> 3;
        int sg  = idx & 7;
        cp_async16(sbase + SKB + (uint32_t)(s * KSTR + sg * 8) * 2,
                   &kb[s * DD + sg * 8]);
        cp_async16(sbase + SVB + (uint32_t)(s * KSTR + sg * 8) * 2,
                   &vb[s * DD + sg * 8]);
    }
    CP_COMMIT();

    // lane-constant ldmatrix bases
    const uint32_t kbase = sbase + SKB +
        ((uint32_t)(wn * 128 + (lane & 7) + ((lane >> 4) & 1) * 8) * KSTR
         + ((lane >> 3) & 1) * 8) * 2;
    const uint32_t vbase = sbase + SVB +
        ((uint32_t)(wn * 128 + (lane & 7) + ((lane >> 3) & 1) * 8) * KSTR
         + ((lane >> 4) & 1) * 8) * 2;

    const float SC = 0.03125f;          // C^-0.5

    bool staged = false;
    for (int t = 0; t < 4; t++) {
        const int q0 = t * 64;
        const int rg0 = q0 + wm * 16 + lr;   // global q row (low)
        const int rg1 = rg0 + 8;

        // ---- Q fragments for this tile (L2-hot gmem loads) ----
        uint32_t qf[4][4];
        {
            const uint32_t* q32 =
                (const uint32_t*)(g_qh + (size_t)(bb * TT + q0 + wm * 16 + lr) * DD);
            const uint32_t* q32b = q32 + 8 * 32;
            #pragma unroll
            for (int ks = 0; ks < 4; ks++) {
                qf[ks][0] = q32 [ks * 8 + lc];
                qf[ks][1] = q32b[ks * 8 + lc];
                qf[ks][2] = q32 [ks * 8 + lc + 4];
                qf[ks][3] = q32b[ks * 8 + lc + 4];
            }
        }
        if (!staged) {
            CP_WAIT0();
            __syncthreads();
            staged = true;
        }

        const int ntv = min(16, max(0, (q0 + 64 - wn * 128) / 8));
        const int ng2 = ntv >> 1;            // 16-key groups

        // ---- QK^T + exp fused; P in registers ----
        uint32_t pf[8][4];
        float srow[2] = {0.f, 0.f};
        #pragma unroll
        for (int g = 0; g < 8; g++) {
            if (g >= ng2) break;
            float s0[4] = {0.f, 0.f, 0.f, 0.f};
            float s1[4] = {0.f, 0.f, 0.f, 0.f};
            #pragma unroll
            for (int ks = 0; ks < 4; ks++) {
                uint32_t bf[4];
                ldmatrix_x4(bf, kbase + g * (16 * KSTR * 2) + ks * 32);
                mma_f16_16n8k16(s0, qf[ks], &bf[0]);
                mma_f16_16n8k16(s1, qf[ks], &bf[2]);
            }
            const int cb = wn * 128 + g * 16 + 2 * lc;
            float e00 = (cb     <= rg0) ? __expf(s0[0] * SC) : 0.f;
            float e01 = (cb + 1 <= rg0) ? __expf(s0[1] * SC) : 0.f;
            float e02 = (cb     <= rg1) ? __expf(s0[2] * SC) : 0.f;
            float e03 = (cb + 1 <= rg1) ? __expf(s0[3] * SC) : 0.f;
            float e10 = (cb + 8 <= rg0) ? __expf(s1[0] * SC) : 0.f;
            float e11 = (cb + 9 <= rg0) ? __expf(s1[1] * SC) : 0.f;
            float e12 = (cb + 8 <= rg1) ? __expf(s1[2] * SC) : 0.f;
            float e13 = (cb + 9 <= rg1) ? __expf(s1[3] * SC) : 0.f;
            srow[0] += e00 + e01 + e10 + e11;
            srow[1] += e02 + e03 + e12 + e13;
            pf[g][0] = pack_h2(e00, e01);
            pf[g][1] = pack_h2(e02, e03);
            pf[g][2] = pack_h2(e10, e11);
            pf[g][3] = pack_h2(e12, e13);
        }

        #pragma unroll
        for (int off = 1; off <= 2; off <<= 1) {
            srow[0] += __shfl_xor_sync(0xFFFFFFFF, srow[0], off);
            srow[1] += __shfl_xor_sync(0xFFFFFFFF, srow[1], off);
        }
        if (lc == 0) {
            sRed[wn * 64 + wm * 16 + lr]     = srow[0];
            sRed[wn * 64 + wm * 16 + lr + 8] = srow[1];
        }
        __syncthreads();

        const float inv0 = 1.f / (sRed[wm * 16 + lr]     + sRed[64 + wm * 16 + lr]);
        const float inv1 = 1.f / (sRed[wm * 16 + lr + 8] + sRed[64 + wm * 16 + lr + 8]);

        // ---- PV: A-fragments straight from pf ----
        float oacc[8][4];
        #pragma unroll
        for (int nt = 0; nt < 8; nt++)
            #pragma unroll
            for (int i = 0; i < 4; i++) oacc[nt][i] = 0.f;

        #pragma unroll
        for (int g = 0; g < 8; g++) {
            if (g >= ng2) break;
            #pragma unroll
            for (int pr = 0; pr < 4; pr++) {
                uint32_t bf[4];
                ldmatrix_x4_trans(bf, vbase + g * (16 * KSTR * 2) + pr * 32);
                mma_f16_16n8k16(oacc[2*pr],     pf[g], &bf[0]);
                mma_f16_16n8k16(oacc[2*pr + 1], pf[g], &bf[2]);
            }
        }

        // ---- cross-warp_n reduction + output ----
        if (wn == 0) {
            #pragma unroll
            for (int nt = 0; nt < 8; nt++) {
                float* o0 = sO + (wm * 16 + lr) * SO_STRIDE + nt * 8 + 2 * lc;
                *(float2*)o0 = make_float2(oacc[nt][0], oacc[nt][1]);
                float* o1 = o0 + 8 * SO_STRIDE;
                *(float2*)o1 = make_float2(oacc[nt][2], oacc[nt][3]);
            }
        }
        __syncthreads();
        if (wn == 1) {
            const size_t orow = (size_t)(bb * TT + q0 + wm * 16 + lr) * DD;
            #pragma unroll
            for (int nt = 0; nt < 8; nt++) {
                const float* o0 = sO + (wm * 16 + lr) * SO_STRIDE + nt * 8 + 2 * lc;
                const float* o1 = o0 + 8 * SO_STRIDE;
                float2 r0v = make_float2((oacc[nt][0] + o0[0]) * inv0,
                                         (oacc[nt][1] + o0[1]) * inv0);
                float2 r1v = make_float2((oacc[nt][2] + o1[0]) * inv1,
                                         (oacc[nt][3] + o1[1]) * inv1);
                *(float2*)&out[orow + nt * 8 + 2 * lc] = r0v;
                *(float2*)&out[orow + 8 * DD + nt * 8 + 2 * lc] = r1v;
            }
        }
        __syncthreads();   // sO + sRed reusable next tile
    }
}

// ---------------------------------------------------------------------------
extern "C" void kernel_launch(void* const* d_in, const int* in_sizes, int n_in,
                              void* d_out, int out_size)
{
    (void)in_sizes; (void)n_in; (void)out_size;
    const float* x  = (const float*)d_in[0];
    const float* Wq = (const float*)d_in[1];
    const float* Wk = (const float*)d_in[2];
    const float* Wv = (const float*)d_in[3];
    float* out = (float*)d_out;

    cudaFuncSetAttribute(qkv_mma_kernel,
                         cudaFuncAttributeMaxDynamicSharedMemorySize, QKV_SMEM);
    cudaFuncSetAttribute(attn_kernel,
                         cudaFuncAttributeMaxDynamicSharedMemorySize, ATT_SMEM);

    transpose_w_kernel<<<48, 256>>>(Wq, Wk, Wv);
    qkv_mma_kernel<<<BT / 64, 256, QKV_SMEM>>>(x);
    attn_kernel<<<BB, 256, ATT_SMEM>>>(out);
}